// round 11
// baseline (speedup 1.0000x reference)
#include <cuda_runtime.h>
#include <cuda_bf16.h>
#include <math_constants.h>
#include <cstdint>

#define MAXN 50000
#define MAXE 500000
#define C    128
#define RELS 3
#define KS   (RELS * C)   // 384 stacked K

// ---------------- scratch (static device memory; no allocation) ----------------
__device__ __align__(16) __nv_bfloat16 g_agg_hi[(size_t)MAXN * KS];
__device__ __align__(16) __nv_bfloat16 g_agg_lo[(size_t)MAXN * KS];
__device__ __align__(16) float g_h[(size_t)MAXN * C];
__device__ unsigned g_pack[MAXE];    // (r<<28)|src in CSR order (built once per launch)
__device__ float    g_attrc[MAXE];   // edge_attr in CSR order
__device__ float g_sq[RELS * MAXN];
__device__ float g_sk[RELS * MAXN];
__device__ __align__(16) float g_wq[RELS * C];
__device__ __align__(16) float g_wk[RELS * C];
__device__ float g_cattr;
__device__ __align__(16) __nv_bfloat16 g_wts_hi[C * KS];
__device__ __align__(16) __nv_bfloat16 g_wts_lo[C * KS];
__device__ int g_deg[MAXN];          // zero-init; re-zeroed by k_scanC each replay
__device__ int g_incl[MAXN];
__device__ int g_indptr[MAXN + 1];
__device__ int g_cursor[MAXN];
__device__ int g_bsum[64];

__device__ __forceinline__ uint32_t smem_u32(const void* p) {
    uint32_t a;
    asm("{ .reg .u64 t; cvta.to.shared.u64 t, %1; cvt.u32.u64 %0, t; }" : "=r"(a) : "l"(p));
    return a;
}
__device__ __forceinline__ void mma_bf16(float* c, const uint32_t* a, const uint32_t* b) {
    asm volatile(
        "mma.sync.aligned.m16n8k16.row.col.f32.bf16.bf16.f32 "
        "{%0,%1,%2,%3}, {%4,%5,%6,%7}, {%8,%9}, {%0,%1,%2,%3};"
        : "+f"(c[0]), "+f"(c[1]), "+f"(c[2]), "+f"(c[3])
        : "r"(a[0]), "r"(a[1]), "r"(a[2]), "r"(a[3]), "r"(b[0]), "r"(b[1]));
}
__device__ __forceinline__ void ldsm_x4(uint32_t* r, uint32_t addr) {
    asm volatile("ldmatrix.sync.aligned.m8n8.x4.shared.b16 {%0,%1,%2,%3}, [%4];"
                 : "=r"(r[0]), "=r"(r[1]), "=r"(r[2]), "=r"(r[3]) : "r"(addr));
}
__device__ __forceinline__ void store_split(__nv_bfloat16* hp, __nv_bfloat16* lp, float4 a) {
    __nv_bfloat16 h0 = __float2bfloat16(a.x), h1 = __float2bfloat16(a.y);
    __nv_bfloat16 h2 = __float2bfloat16(a.z), h3 = __float2bfloat16(a.w);
    __nv_bfloat162 hh0(h0, h1), hh1(h2, h3);
    __nv_bfloat162 ll0(__float2bfloat16(a.x - __bfloat162float(h0)),
                       __float2bfloat16(a.y - __bfloat162float(h1)));
    __nv_bfloat162 ll1(__float2bfloat16(a.z - __bfloat162float(h2)),
                       __float2bfloat16(a.w - __bfloat162float(h3)));
    ((__nv_bfloat162*)hp)[0] = hh0; ((__nv_bfloat162*)hp)[1] = hh1;
    ((__nv_bfloat162*)lp)[0] = ll0; ((__nv_bfloat162*)lp)[1] = ll1;
}

// ---------------- CSR build ----------------
__global__ void k_count(const int* __restrict__ dst, int e_cnt) {
    int e = blockIdx.x * blockDim.x + threadIdx.x;
    if (e < e_cnt) atomicAdd(&g_deg[dst[e]], 1);
}
__global__ void k_scanA(int n) {
    __shared__ int sh[2][1024];
    int tid = threadIdx.x;
    int i = blockIdx.x * 1024 + tid;
    int v = (i < n) ? g_deg[i] : 0;
    sh[0][tid] = v;
    __syncthreads();
    int pb = 0;
#pragma unroll
    for (int off = 1; off < 1024; off <<= 1) {
        int nb = pb ^ 1;
        int val = sh[pb][tid];
        if (tid >= off) val += sh[pb][tid - off];
        sh[nb][tid] = val;
        pb = nb;
        __syncthreads();
    }
    int incl = sh[pb][tid];
    if (i < n) g_incl[i] = incl;
    if (tid == 1023) g_bsum[blockIdx.x] = incl;
}
__global__ void k_scanC(int n, int nblk) {
    __shared__ int sb[64];
    int tid = threadIdx.x;
    int bid = blockIdx.x;
    if (tid < 64) sb[tid] = (tid < nblk) ? g_bsum[tid] : 0;
    __syncthreads();
#pragma unroll
    for (int off = 1; off < 64; off <<= 1) {
        int add = (tid < 64 && tid >= off) ? sb[tid - off] : 0;
        __syncthreads();
        if (tid < 64) sb[tid] += add;
        __syncthreads();
    }
    int base = (bid == 0) ? 0 : sb[bid - 1];
    int i = bid * 1024 + tid;
    if (i < n) {
        int total = g_incl[i] + base;
        g_indptr[i + 1] = total;
        g_cursor[i] = total - g_deg[i];
        g_deg[i] = 0;
        if (i == 0) g_indptr[0] = 0;
    }
}
// scatter (r|src) + attr into CSR slots (once; reused by both layers)
__global__ void k_fill(const int* __restrict__ src, const int* __restrict__ dst,
                       const int* __restrict__ etype, const float* __restrict__ attr,
                       int e_cnt) {
    int e = blockIdx.x * blockDim.x + threadIdx.x;
    if (e >= e_cnt) return;
    int pos = atomicAdd(&g_cursor[dst[e]], 1);
    g_pack[pos] = (unsigned)src[e] | ((unsigned)etype[e] << 28);
    g_attrc[pos] = attr[e];
}

// ---------------- per-layer precompute (tiled W transpose-split + wq/wk/cattr) ----------------
__global__ void k_prepall(const float* __restrict__ w, const float* __restrict__ q,
                          const float* __restrict__ kk, const float* __restrict__ le,
                          const float* __restrict__ ee) {
    if (blockIdx.x < 2 * RELS) {
        __shared__ float tile[64][129];
        int r = blockIdx.x >> 1;
        int kt = (blockIdx.x & 1) * 64;
        const float* Wr = w + (size_t)r * C * C;
        int tid = threadIdx.x;
#pragma unroll
        for (int it = 0; it < 8; ++it) {
            int idx = tid + it * 256;
            int kkr = idx >> 5;
            int nn4 = (idx & 31) * 4;
            float4 v = *(const float4*)(Wr + (size_t)(kt + kkr) * C + nn4);
            tile[kkr][nn4] = v.x; tile[kkr][nn4 + 1] = v.y;
            tile[kkr][nn4 + 2] = v.z; tile[kkr][nn4 + 3] = v.w;
        }
        __syncthreads();
        int lane = tid & 31, wid = tid >> 5;
        for (int nn = wid; nn < C; nn += 8) {
            float v0 = tile[2 * lane][nn];
            float v1 = tile[2 * lane + 1][nn];
            __nv_bfloat16 h0 = __float2bfloat16(v0), h1 = __float2bfloat16(v1);
            __nv_bfloat162 hh(h0, h1);
            __nv_bfloat162 ll(__float2bfloat16(v0 - __bfloat162float(h0)),
                              __float2bfloat16(v1 - __bfloat162float(h1)));
            size_t off = (size_t)nn * KS + r * C + kt + 2 * lane;
            *(__nv_bfloat162*)(g_wts_hi + off) = hh;
            *(__nv_bfloat162*)(g_wts_lo + off) = ll;
        }
        return;
    }
    int gw = (blockIdx.x - 2 * RELS) * 8 + (threadIdx.x >> 5);
    int lane = threadIdx.x & 31;
    if (gw < RELS * C) {
        const float4* row = (const float4*)(w + (size_t)gw * C);
        float4 wv = row[lane];
        float4 qv = ((const float4*)q)[lane];
        float4 kv = ((const float4*)kk)[lane];
        float aq = wv.x * qv.x + wv.y * qv.y + wv.z * qv.z + wv.w * qv.w;
        float ak = wv.x * kv.x + wv.y * kv.y + wv.z * kv.z + wv.w * kv.w;
#pragma unroll
        for (int off = 16; off; off >>= 1) {
            aq += __shfl_xor_sync(0xffffffffu, aq, off);
            ak += __shfl_xor_sync(0xffffffffu, ak, off);
        }
        if (lane == 0) { g_wq[gw] = aq; g_wk[gw] = ak; }
    } else if (gw == RELS * C) {
        float p = 0.f;
        for (int o = lane; o < C; o += 32) p += le[o] * ee[o];
#pragma unroll
        for (int off = 16; off; off >>= 1) p += __shfl_xor_sync(0xffffffffu, p, off);
        if (lane == 0) g_cattr = p;
    }
}

// ---------------- per-node attention scalars ----------------
__global__ void k_sqk(const float* __restrict__ x, int n) {
    int gw = (blockIdx.x * blockDim.x + threadIdx.x) >> 5;
    int lane = threadIdx.x & 31;
    if (gw >= n) return;
    float4 xv = ((const float4*)x)[(size_t)gw * 32 + lane];
    float aq[RELS], ak[RELS];
#pragma unroll
    for (int r = 0; r < RELS; ++r) {
        float4 wqv = ((const float4*)g_wq)[r * 32 + lane];
        float4 wkv = ((const float4*)g_wk)[r * 32 + lane];
        aq[r] = xv.x * wqv.x + xv.y * wqv.y + xv.z * wqv.z + xv.w * wqv.w;
        ak[r] = xv.x * wkv.x + xv.y * wkv.y + xv.z * wkv.z + xv.w * wkv.w;
    }
#pragma unroll
    for (int off = 16; off; off >>= 1) {
#pragma unroll
        for (int r = 0; r < RELS; ++r) {
            aq[r] += __shfl_xor_sync(0xffffffffu, aq[r], off);
            ak[r] += __shfl_xor_sync(0xffffffffu, ak[r], off);
        }
    }
    if (lane == 0) {
#pragma unroll
        for (int r = 0; r < RELS; ++r) {
            g_sq[r * n + gw] = aq[r];
            g_sk[r * n + gw] = ak[r];
        }
    }
}

// ---------------- per-node: inline alpha + online softmax + aggregate -> bf16 split ----------------
#define ACCUM(rr, co, v)                                                     \
    do {                                                                     \
        if ((rr) == 0) {                                                     \
            a0.x = fmaf(co, (v).x, a0.x); a0.y = fmaf(co, (v).y, a0.y);      \
            a0.z = fmaf(co, (v).z, a0.z); a0.w = fmaf(co, (v).w, a0.w);      \
        } else if ((rr) == 1) {                                              \
            a1.x = fmaf(co, (v).x, a1.x); a1.y = fmaf(co, (v).y, a1.y);      \
            a1.z = fmaf(co, (v).z, a1.z); a1.w = fmaf(co, (v).w, a1.w);      \
        } else {                                                             \
            a2.x = fmaf(co, (v).x, a2.x); a2.y = fmaf(co, (v).y, a2.y);      \
            a2.z = fmaf(co, (v).z, a2.z); a2.w = fmaf(co, (v).w, a2.w);      \
        }                                                                    \
    } while (0)

__global__ void k_agg(const float* __restrict__ xin, int n) {
    int gw = (blockIdx.x * blockDim.x + threadIdx.x) >> 5;
    int lane = threadIdx.x & 31;
    if (gw >= n) return;
    int beg = g_indptr[gw], end = g_indptr[gw + 1];

    float sq0 = g_sq[gw], sq1 = g_sq[n + gw], sq2 = g_sq[2 * n + gw];
    float ca = g_cattr;

    // single-pass online softmax over strided edges
    float m = -1e30f, s = 0.f;
    for (int j = beg + lane; j < end; j += 32) {
        unsigned p = g_pack[j];
        unsigned sv = p & 0x0FFFFFFFu, r = p >> 28;
        float a = (r == 0 ? sq0 : (r == 1 ? sq1 : sq2)) + g_sk[r * n + sv] + ca * g_attrc[j];
        a = (a > 0.f) ? a : 0.2f * a;
        if (a > m) { s *= __expf(m - a); m = a; }
        s += __expf(a - m);
    }
#pragma unroll
    for (int off = 16; off; off >>= 1) {
        float mo = __shfl_xor_sync(0xffffffffu, m, off);
        float so = __shfl_xor_sync(0xffffffffu, s, off);
        float mn = fmaxf(m, mo);
        s = s * __expf(m - mn) + so * __expf(mo - mn);
        m = mn;
    }
    float inv = 1.f / (s + 1e-16f);

    // weighted gather (alpha recomputed, broadcast loads)
    float4 a0 = make_float4(0.f, 0.f, 0.f, 0.f);
    float4 a1 = a0, a2 = a0;
    int j = beg;
    for (; j + 1 < end; j += 2) {
        unsigned p0 = g_pack[j], p1 = g_pack[j + 1];
        unsigned s0 = p0 & 0x0FFFFFFFu, r0 = p0 >> 28;
        unsigned s1 = p1 & 0x0FFFFFFFu, r1 = p1 >> 28;
        float4 v0 = ((const float4*)(xin + (size_t)s0 * C))[lane];
        float4 v1 = ((const float4*)(xin + (size_t)s1 * C))[lane];
        float al0 = (r0 == 0 ? sq0 : (r0 == 1 ? sq1 : sq2)) + g_sk[r0 * n + s0] + ca * g_attrc[j];
        float al1 = (r1 == 0 ? sq0 : (r1 == 1 ? sq1 : sq2)) + g_sk[r1 * n + s1] + ca * g_attrc[j + 1];
        al0 = (al0 > 0.f) ? al0 : 0.2f * al0;
        al1 = (al1 > 0.f) ? al1 : 0.2f * al1;
        float c0 = __expf(al0 - m) * inv;
        float c1 = __expf(al1 - m) * inv;
        ACCUM(r0, c0, v0);
        ACCUM(r1, c1, v1);
    }
    if (j < end) {
        unsigned p0 = g_pack[j];
        unsigned s0 = p0 & 0x0FFFFFFFu, r0 = p0 >> 28;
        float4 v0 = ((const float4*)(xin + (size_t)s0 * C))[lane];
        float al0 = (r0 == 0 ? sq0 : (r0 == 1 ? sq1 : sq2)) + g_sk[r0 * n + s0] + ca * g_attrc[j];
        al0 = (al0 > 0.f) ? al0 : 0.2f * al0;
        float c0 = __expf(al0 - m) * inv;
        ACCUM(r0, c0, v0);
    }
    size_t ob = (size_t)gw * KS + (size_t)lane * 4;
    store_split(g_agg_hi + ob,         g_agg_lo + ob,         a0);
    store_split(g_agg_hi + ob + C,     g_agg_lo + ob + C,     a1);
    store_split(g_agg_hi + ob + 2 * C, g_agg_lo + ob + 2 * C, a2);
}

// ---------------- stacked HMMA bf16 3-term GEMM: out = agg @ Wstack + bias (opt relu) ----------------
#define APADB 72
#define GEMM_SMEM (4 * 128 * APADB * 2)

__global__ __launch_bounds__(256, 2) void k_gemm_st(const float* __restrict__ bias,
                                                    float* __restrict__ out,
                                                    int relu, int n) {
    extern __shared__ __nv_bfloat16 smb[];
    __nv_bfloat16* Ah = smb;
    __nv_bfloat16* Al = Ah + 128 * APADB;
    __nv_bfloat16* Bh = Al + 128 * APADB;
    __nv_bfloat16* Bl = Bh + 128 * APADB;

    int m0 = blockIdx.x * 128;
    int tid = threadIdx.x;
    int lane = tid & 31;
    int wid = tid >> 5;
    int wm = wid & 1;
    int wn = wid >> 1;

    uint32_t aAh = smem_u32(Ah), aAl = smem_u32(Al);
    uint32_t aBh = smem_u32(Bh), aBl = smem_u32(Bl);

    int lrow = (lane & 7) + ((lane >> 3) & 1) * 8;
    int lkoff = (lane >> 4) * 8;
    uint32_t baseA = (uint32_t)((wm * 64 + lrow) * APADB + lkoff) * 2;
    uint32_t baseB = (uint32_t)((wn * 32 + lrow) * APADB + lkoff) * 2;

    float acc[4][4][4];
#pragma unroll
    for (int a = 0; a < 4; ++a)
#pragma unroll
        for (int b = 0; b < 4; ++b)
#pragma unroll
            for (int cc = 0; cc < 4; ++cc) acc[a][b][cc] = 0.f;

    const uint4 zero4 = make_uint4(0u, 0u, 0u, 0u);
    int u4 = tid & 7;
    int rb = tid >> 3;

#pragma unroll 1
    for (int kc = 0; kc < KS; kc += 64) {
#pragma unroll
        for (int it = 0; it < 4; ++it) {
            int row = rb + it * 32;
            uint4 vh = zero4, vl = zero4;
            if (m0 + row < n) {
                size_t goff = (size_t)(m0 + row) * KS + kc + u4 * 8;
                vh = *(const uint4*)(g_agg_hi + goff);
                vl = *(const uint4*)(g_agg_lo + goff);
            }
            *(uint4*)(Ah + row * APADB + u4 * 8) = vh;
            *(uint4*)(Al + row * APADB + u4 * 8) = vl;
        }
#pragma unroll
        for (int it = 0; it < 4; ++it) {
            int nn = rb + it * 32;
            size_t goff = (size_t)nn * KS + kc + u4 * 8;
            *(uint4*)(Bh + nn * APADB + u4 * 8) = *(const uint4*)(g_wts_hi + goff);
            *(uint4*)(Bl + nn * APADB + u4 * 8) = *(const uint4*)(g_wts_lo + goff);
        }
        __syncthreads();

#pragma unroll
        for (int ks = 0; ks < 4; ++ks) {
            uint32_t koff = (uint32_t)(ks * 16) * 2;
            uint32_t ah[4][4], al[4][4], bh[4][2], bl[4][2];
#pragma unroll
            for (int mt = 0; mt < 4; ++mt) {
                ldsm_x4(ah[mt], aAh + baseA + koff + (uint32_t)(mt * 16 * APADB * 2));
                ldsm_x4(al[mt], aAl + baseA + koff + (uint32_t)(mt * 16 * APADB * 2));
            }
#pragma unroll
            for (int p = 0; p < 2; ++p) {
                uint32_t t4[4];
                ldsm_x4(t4, aBh + baseB + koff + (uint32_t)(p * 16 * APADB * 2));
                bh[2 * p][0] = t4[0]; bh[2 * p + 1][0] = t4[1];
                bh[2 * p][1] = t4[2]; bh[2 * p + 1][1] = t4[3];
                ldsm_x4(t4, aBl + baseB + koff + (uint32_t)(p * 16 * APADB * 2));
                bl[2 * p][0] = t4[0]; bl[2 * p + 1][0] = t4[1];
                bl[2 * p][1] = t4[2]; bl[2 * p + 1][1] = t4[3];
            }
#pragma unroll
            for (int mt = 0; mt < 4; ++mt)
#pragma unroll
                for (int nt = 0; nt < 4; ++nt) mma_bf16(acc[mt][nt], ah[mt], bh[nt]);
#pragma unroll
            for (int mt = 0; mt < 4; ++mt)
#pragma unroll
                for (int nt = 0; nt < 4; ++nt) mma_bf16(acc[mt][nt], ah[mt], bl[nt]);
#pragma unroll
            for (int mt = 0; mt < 4; ++mt)
#pragma unroll
                for (int nt = 0; nt < 4; ++nt) mma_bf16(acc[mt][nt], al[mt], bh[nt]);
        }
        __syncthreads();
    }

    float bx[4][2];
#pragma unroll
    for (int nt = 0; nt < 4; ++nt) {
        int col = wn * 32 + nt * 8 + 2 * (lane & 3);
        bx[nt][0] = bias[col];
        bx[nt][1] = bias[col + 1];
    }
#pragma unroll
    for (int mt = 0; mt < 4; ++mt) {
        int row0 = m0 + wm * 64 + mt * 16 + (lane >> 2);
        int row1 = row0 + 8;
#pragma unroll
        for (int nt = 0; nt < 4; ++nt) {
            int col = wn * 32 + nt * 8 + 2 * (lane & 3);
            float2 o0 = make_float2(acc[mt][nt][0] + bx[nt][0], acc[mt][nt][1] + bx[nt][1]);
            float2 o1 = make_float2(acc[mt][nt][2] + bx[nt][0], acc[mt][nt][3] + bx[nt][1]);
            if (relu) {
                o0.x = fmaxf(o0.x, 0.f); o0.y = fmaxf(o0.y, 0.f);
                o1.x = fmaxf(o1.x, 0.f); o1.y = fmaxf(o1.y, 0.f);
            }
            if (row0 < n) *(float2*)(out + (size_t)row0 * C + col) = o0;
            if (row1 < n) *(float2*)(out + (size_t)row1 * C + col) = o1;
        }
    }
}

// ---------------- driver ----------------
extern "C" void kernel_launch(void* const* d_in, const int* in_sizes, int n_in,
                              void* d_out, int out_size) {
    const float* x    = (const float*)d_in[0];
    const int*   ei   = (const int*)d_in[1];
    const int*   et   = (const int*)d_in[2];
    const float* attr = (const float*)d_in[3];
    const float *w1 = (const float*)d_in[4],  *q1 = (const float*)d_in[5],
                *k1 = (const float*)d_in[6],  *le1 = (const float*)d_in[7],
                *e1 = (const float*)d_in[8],  *b1 = (const float*)d_in[9];
    const float *w2 = (const float*)d_in[10], *q2 = (const float*)d_in[11],
                *k2 = (const float*)d_in[12], *le2 = (const float*)d_in[13],
                *e2 = (const float*)d_in[14], *b2 = (const float*)d_in[15];

    int n = in_sizes[0] / C;
    int e_cnt = in_sizes[2];
    const int* src = ei;
    const int* dst = ei + e_cnt;

    float* h = nullptr;
    cudaGetSymbolAddress((void**)&h, g_h);

    static bool attr_set = false;
    if (!attr_set) {
        cudaFuncSetAttribute(k_gemm_st, cudaFuncAttributeMaxDynamicSharedMemorySize, GEMM_SMEM);
        attr_set = true;
    }

    int nblk = (n + 1023) / 1024;
    int prep_grid = 2 * RELS + (RELS * C + 1 + 7) / 8;
    int gemm_grid = (n + 127) / 128;

    // CSR build + one-time edge scatter (pack + attr in CSR order)
    k_count<<<(e_cnt + 255) / 256, 256>>>(dst, e_cnt);
    k_scanA<<<nblk, 1024>>>(n);
    k_scanC<<<nblk, 1024>>>(n, nblk);
    k_fill<<<(e_cnt + 255) / 256, 256>>>(src, dst, et, attr, e_cnt);

    // layer 1
    k_prepall<<<prep_grid, 256>>>(w1, q1, k1, le1, e1);
    k_sqk<<<(n + 7) / 8, 256>>>(x, n);
    k_agg<<<(n + 7) / 8, 256>>>(x, n);
    k_gemm_st<<<gemm_grid, 256, GEMM_SMEM>>>(b1, h, 1, n);

    // layer 2
    k_prepall<<<prep_grid, 256>>>(w2, q2, k2, le2, e2);
    k_sqk<<<(n + 7) / 8, 256>>>(h, n);
    k_agg<<<(n + 7) / 8, 256>>>(h, n);
    k_gemm_st<<<gemm_grid, 256, GEMM_SMEM>>>(b2, (float*)d_out, 0, n);
}

// round 12
// speedup vs baseline: 1.0006x; 1.0006x over previous
#include <cuda_runtime.h>
#include <cuda_bf16.h>
#include <math_constants.h>
#include <cstdint>

#define MAXN 50000
#define MAXE 500000
#define C    128
#define RELS 3
#define KS   (RELS * C)   // 384 stacked K

// ---------------- scratch (static device memory; no allocation) ----------------
__device__ __align__(16) __nv_bfloat16 g_agg_hi[(size_t)MAXN * KS];
__device__ __align__(16) __nv_bfloat16 g_agg_lo[(size_t)MAXN * KS];
__device__ __align__(16) float g_h[(size_t)MAXN * C];
__device__ unsigned g_pack[MAXE];    // (r<<28)|src in CSR order (built once per launch)
__device__ float    g_attrc[MAXE];   // edge_attr in CSR order
__device__ float g_sq[RELS * MAXN];
__device__ float g_sk[RELS * MAXN];
__device__ __align__(16) float g_wq[RELS * C];
__device__ __align__(16) float g_wk[RELS * C];
__device__ float g_cattr;
__device__ __align__(16) __nv_bfloat16 g_wts_hi[C * KS];
__device__ __align__(16) __nv_bfloat16 g_wts_lo[C * KS];
__device__ int g_deg[MAXN];          // zero-init; re-zeroed by k_scanC each replay
__device__ int g_incl[MAXN];
__device__ int g_indptr[MAXN + 1];
__device__ int g_cursor[MAXN];
__device__ int g_bsum[64];

__device__ __forceinline__ uint32_t smem_u32(const void* p) {
    uint32_t a;
    asm("{ .reg .u64 t; cvta.to.shared.u64 t, %1; cvt.u32.u64 %0, t; }" : "=r"(a) : "l"(p));
    return a;
}
__device__ __forceinline__ void mma_bf16(float* c, const uint32_t* a, const uint32_t* b) {
    asm volatile(
        "mma.sync.aligned.m16n8k16.row.col.f32.bf16.bf16.f32 "
        "{%0,%1,%2,%3}, {%4,%5,%6,%7}, {%8,%9}, {%0,%1,%2,%3};"
        : "+f"(c[0]), "+f"(c[1]), "+f"(c[2]), "+f"(c[3])
        : "r"(a[0]), "r"(a[1]), "r"(a[2]), "r"(a[3]), "r"(b[0]), "r"(b[1]));
}
__device__ __forceinline__ void ldsm_x4(uint32_t* r, uint32_t addr) {
    asm volatile("ldmatrix.sync.aligned.m8n8.x4.shared.b16 {%0,%1,%2,%3}, [%4];"
                 : "=r"(r[0]), "=r"(r[1]), "=r"(r[2]), "=r"(r[3]) : "r"(addr));
}
__device__ __forceinline__ void store_split(__nv_bfloat16* hp, __nv_bfloat16* lp, float4 a) {
    __nv_bfloat16 h0 = __float2bfloat16(a.x), h1 = __float2bfloat16(a.y);
    __nv_bfloat16 h2 = __float2bfloat16(a.z), h3 = __float2bfloat16(a.w);
    __nv_bfloat162 hh0(h0, h1), hh1(h2, h3);
    __nv_bfloat162 ll0(__float2bfloat16(a.x - __bfloat162float(h0)),
                       __float2bfloat16(a.y - __bfloat162float(h1)));
    __nv_bfloat162 ll1(__float2bfloat16(a.z - __bfloat162float(h2)),
                       __float2bfloat16(a.w - __bfloat162float(h3)));
    ((__nv_bfloat162*)hp)[0] = hh0; ((__nv_bfloat162*)hp)[1] = hh1;
    ((__nv_bfloat162*)lp)[0] = ll0; ((__nv_bfloat162*)lp)[1] = ll1;
}

// ---------------- CSR build ----------------
__global__ void k_count(const int* __restrict__ dst, int e_cnt) {
    int e = blockIdx.x * blockDim.x + threadIdx.x;
    if (e < e_cnt) atomicAdd(&g_deg[dst[e]], 1);
}
__global__ void k_scanA(int n) {
    __shared__ int sh[2][1024];
    int tid = threadIdx.x;
    int i = blockIdx.x * 1024 + tid;
    int v = (i < n) ? g_deg[i] : 0;
    sh[0][tid] = v;
    __syncthreads();
    int pb = 0;
#pragma unroll
    for (int off = 1; off < 1024; off <<= 1) {
        int nb = pb ^ 1;
        int val = sh[pb][tid];
        if (tid >= off) val += sh[pb][tid - off];
        sh[nb][tid] = val;
        pb = nb;
        __syncthreads();
    }
    int incl = sh[pb][tid];
    if (i < n) g_incl[i] = incl;
    if (tid == 1023) g_bsum[blockIdx.x] = incl;
}
__global__ void k_scanC(int n, int nblk) {
    __shared__ int sb[64];
    int tid = threadIdx.x;
    int bid = blockIdx.x;
    if (tid < 64) sb[tid] = (tid < nblk) ? g_bsum[tid] : 0;
    __syncthreads();
#pragma unroll
    for (int off = 1; off < 64; off <<= 1) {
        int add = (tid < 64 && tid >= off) ? sb[tid - off] : 0;
        __syncthreads();
        if (tid < 64) sb[tid] += add;
        __syncthreads();
    }
    int base = (bid == 0) ? 0 : sb[bid - 1];
    int i = bid * 1024 + tid;
    if (i < n) {
        int total = g_incl[i] + base;
        g_indptr[i + 1] = total;
        g_cursor[i] = total - g_deg[i];
        g_deg[i] = 0;
        if (i == 0) g_indptr[0] = 0;
    }
}
// scatter (r|src) + attr into CSR slots (once; reused by both layers)
__global__ void k_fill(const int* __restrict__ src, const int* __restrict__ dst,
                       const int* __restrict__ etype, const float* __restrict__ attr,
                       int e_cnt) {
    int e = blockIdx.x * blockDim.x + threadIdx.x;
    if (e >= e_cnt) return;
    int pos = atomicAdd(&g_cursor[dst[e]], 1);
    g_pack[pos] = (unsigned)src[e] | ((unsigned)etype[e] << 28);
    g_attrc[pos] = attr[e];
}

// ---------------- per-layer precompute (tiled W transpose-split + wq/wk/cattr) ----------------
__global__ void k_prepall(const float* __restrict__ w, const float* __restrict__ q,
                          const float* __restrict__ kk, const float* __restrict__ le,
                          const float* __restrict__ ee) {
    if (blockIdx.x < 2 * RELS) {
        __shared__ float tile[64][129];
        int r = blockIdx.x >> 1;
        int kt = (blockIdx.x & 1) * 64;
        const float* Wr = w + (size_t)r * C * C;
        int tid = threadIdx.x;
#pragma unroll
        for (int it = 0; it < 8; ++it) {
            int idx = tid + it * 256;
            int kkr = idx >> 5;
            int nn4 = (idx & 31) * 4;
            float4 v = *(const float4*)(Wr + (size_t)(kt + kkr) * C + nn4);
            tile[kkr][nn4] = v.x; tile[kkr][nn4 + 1] = v.y;
            tile[kkr][nn4 + 2] = v.z; tile[kkr][nn4 + 3] = v.w;
        }
        __syncthreads();
        int lane = tid & 31, wid = tid >> 5;
        for (int nn = wid; nn < C; nn += 8) {
            float v0 = tile[2 * lane][nn];
            float v1 = tile[2 * lane + 1][nn];
            __nv_bfloat16 h0 = __float2bfloat16(v0), h1 = __float2bfloat16(v1);
            __nv_bfloat162 hh(h0, h1);
            __nv_bfloat162 ll(__float2bfloat16(v0 - __bfloat162float(h0)),
                              __float2bfloat16(v1 - __bfloat162float(h1)));
            size_t off = (size_t)nn * KS + r * C + kt + 2 * lane;
            *(__nv_bfloat162*)(g_wts_hi + off) = hh;
            *(__nv_bfloat162*)(g_wts_lo + off) = ll;
        }
        return;
    }
    int gw = (blockIdx.x - 2 * RELS) * 8 + (threadIdx.x >> 5);
    int lane = threadIdx.x & 31;
    if (gw < RELS * C) {
        const float4* row = (const float4*)(w + (size_t)gw * C);
        float4 wv = row[lane];
        float4 qv = ((const float4*)q)[lane];
        float4 kv = ((const float4*)kk)[lane];
        float aq = wv.x * qv.x + wv.y * qv.y + wv.z * qv.z + wv.w * qv.w;
        float ak = wv.x * kv.x + wv.y * kv.y + wv.z * kv.z + wv.w * kv.w;
#pragma unroll
        for (int off = 16; off; off >>= 1) {
            aq += __shfl_xor_sync(0xffffffffu, aq, off);
            ak += __shfl_xor_sync(0xffffffffu, ak, off);
        }
        if (lane == 0) { g_wq[gw] = aq; g_wk[gw] = ak; }
    } else if (gw == RELS * C) {
        float p = 0.f;
        for (int o = lane; o < C; o += 32) p += le[o] * ee[o];
#pragma unroll
        for (int off = 16; off; off >>= 1) p += __shfl_xor_sync(0xffffffffu, p, off);
        if (lane == 0) g_cattr = p;
    }
}

// ---------------- per-node attention scalars ----------------
__global__ void k_sqk(const float* __restrict__ x, int n) {
    int gw = (blockIdx.x * blockDim.x + threadIdx.x) >> 5;
    int lane = threadIdx.x & 31;
    if (gw >= n) return;
    float4 xv = ((const float4*)x)[(size_t)gw * 32 + lane];
    float aq[RELS], ak[RELS];
#pragma unroll
    for (int r = 0; r < RELS; ++r) {
        float4 wqv = ((const float4*)g_wq)[r * 32 + lane];
        float4 wkv = ((const float4*)g_wk)[r * 32 + lane];
        aq[r] = xv.x * wqv.x + xv.y * wqv.y + xv.z * wqv.z + xv.w * wqv.w;
        ak[r] = xv.x * wkv.x + xv.y * wkv.y + xv.z * wkv.z + xv.w * wkv.w;
    }
#pragma unroll
    for (int off = 16; off; off >>= 1) {
#pragma unroll
        for (int r = 0; r < RELS; ++r) {
            aq[r] += __shfl_xor_sync(0xffffffffu, aq[r], off);
            ak[r] += __shfl_xor_sync(0xffffffffu, ak[r], off);
        }
    }
    if (lane == 0) {
#pragma unroll
        for (int r = 0; r < RELS; ++r) {
            g_sq[r * n + gw] = aq[r];
            g_sk[r * n + gw] = ak[r];
        }
    }
}

// ---------------- per-node: alpha once (reg-cached) + online softmax + gather ----------------
#define ACCUM(rr, co, v)                                                     \
    do {                                                                     \
        if ((rr) == 0) {                                                     \
            a0.x = fmaf(co, (v).x, a0.x); a0.y = fmaf(co, (v).y, a0.y);      \
            a0.z = fmaf(co, (v).z, a0.z); a0.w = fmaf(co, (v).w, a0.w);      \
        } else if ((rr) == 1) {                                              \
            a1.x = fmaf(co, (v).x, a1.x); a1.y = fmaf(co, (v).y, a1.y);      \
            a1.z = fmaf(co, (v).z, a1.z); a1.w = fmaf(co, (v).w, a1.w);      \
        } else {                                                             \
            a2.x = fmaf(co, (v).x, a2.x); a2.y = fmaf(co, (v).y, a2.y);      \
            a2.z = fmaf(co, (v).z, a2.z); a2.w = fmaf(co, (v).w, a2.w);      \
        }                                                                    \
    } while (0)

__global__ void k_agg(const float* __restrict__ xin, int n) {
    int gw = (blockIdx.x * blockDim.x + threadIdx.x) >> 5;
    int lane = threadIdx.x & 31;
    if (gw >= n) return;
    int beg = g_indptr[gw], end = g_indptr[gw + 1];
    int deg = end - beg;

    float sq0 = g_sq[gw], sq1 = g_sq[n + gw], sq2 = g_sq[2 * n + gw];
    float ca = g_cattr;

    // pass 1: alpha per lane-strided edge, cached in registers; online softmax
    float av[8];
    float m = -1e30f, s = 0.f;
#pragma unroll
    for (int t = 0; t < 8; ++t) {
        int j = beg + lane + t * 32;
        if (j < end) {
            unsigned p = g_pack[j];
            unsigned sv = p & 0x0FFFFFFFu, r = p >> 28;
            float a = (r == 0 ? sq0 : (r == 1 ? sq1 : sq2)) + g_sk[r * n + sv] + ca * g_attrc[j];
            a = (a > 0.f) ? a : 0.2f * a;
            av[t] = a;
            if (a > m) { s *= __expf(m - a); m = a; }
            s += __expf(a - m);
        } else av[t] = 0.f;
    }
    // rare fallback tail (deg > 256): continue online softmax without caching
    for (int j = beg + lane + 256; j < end; j += 32) {
        unsigned p = g_pack[j];
        unsigned sv = p & 0x0FFFFFFFu, r = p >> 28;
        float a = (r == 0 ? sq0 : (r == 1 ? sq1 : sq2)) + g_sk[r * n + sv] + ca * g_attrc[j];
        a = (a > 0.f) ? a : 0.2f * a;
        if (a > m) { s *= __expf(m - a); m = a; }
        s += __expf(a - m);
    }
#pragma unroll
    for (int off = 16; off; off >>= 1) {
        float mo = __shfl_xor_sync(0xffffffffu, m, off);
        float so = __shfl_xor_sync(0xffffffffu, s, off);
        float mn = fmaxf(m, mo);
        s = s * __expf(m - mn) + so * __expf(mo - mn);
        m = mn;
    }
    float inv = 1.f / (s + 1e-16f);

    // pass 2: gather + weighted accumulate; alpha via shfl from owning lane
    float4 a0 = make_float4(0.f, 0.f, 0.f, 0.f);
    float4 a1 = a0, a2 = a0;
    int ndeg = (deg < 256) ? deg : 256;
#pragma unroll
    for (int blk = 0; blk < 8; ++blk) {
        int b0 = blk * 32;
        if (b0 >= ndeg) break;
        float myA = av[blk];
        int lim = ndeg - b0;
        if (lim > 32) lim = 32;
        int t = 0;
        for (; t + 1 < lim; t += 2) {
            int j0 = beg + b0 + t, j1 = j0 + 1;
            float aa0 = __shfl_sync(0xffffffffu, myA, t);
            float aa1 = __shfl_sync(0xffffffffu, myA, t + 1);
            unsigned p0 = g_pack[j0], p1 = g_pack[j1];
            unsigned s0 = p0 & 0x0FFFFFFFu, r0 = p0 >> 28;
            unsigned s1 = p1 & 0x0FFFFFFFu, r1 = p1 >> 28;
            float4 v0 = ((const float4*)(xin + (size_t)s0 * C))[lane];
            float4 v1 = ((const float4*)(xin + (size_t)s1 * C))[lane];
            float c0 = __expf(aa0 - m) * inv;
            float c1 = __expf(aa1 - m) * inv;
            ACCUM(r0, c0, v0);
            ACCUM(r1, c1, v1);
        }
        if (t < lim) {
            int j0 = beg + b0 + t;
            float aa0 = __shfl_sync(0xffffffffu, myA, t);
            unsigned p0 = g_pack[j0];
            unsigned s0 = p0 & 0x0FFFFFFFu, r0 = p0 >> 28;
            float4 v0 = ((const float4*)(xin + (size_t)s0 * C))[lane];
            float c0 = __expf(aa0 - m) * inv;
            ACCUM(r0, c0, v0);
        }
    }
    // rare fallback tail: recompute alpha inline
    for (int j = beg + 256; j < end; ++j) {
        unsigned p = g_pack[j];
        unsigned sv = p & 0x0FFFFFFFu, r = p >> 28;
        float a = (r == 0 ? sq0 : (r == 1 ? sq1 : sq2)) + g_sk[r * n + sv] + ca * g_attrc[j];
        a = (a > 0.f) ? a : 0.2f * a;
        float4 v = ((const float4*)(xin + (size_t)sv * C))[lane];
        float co = __expf(a - m) * inv;
        ACCUM(r, co, v);
    }

    size_t ob = (size_t)gw * KS + (size_t)lane * 4;
    store_split(g_agg_hi + ob,         g_agg_lo + ob,         a0);
    store_split(g_agg_hi + ob + C,     g_agg_lo + ob + C,     a1);
    store_split(g_agg_hi + ob + 2 * C, g_agg_lo + ob + 2 * C, a2);
}

// ---------------- stacked HMMA bf16 3-term GEMM: out = agg @ Wstack + bias (opt relu) ----------------
#define APADB 72
#define GEMM_SMEM (4 * 128 * APADB * 2)

__global__ __launch_bounds__(256, 2) void k_gemm_st(const float* __restrict__ bias,
                                                    float* __restrict__ out,
                                                    int relu, int n) {
    extern __shared__ __nv_bfloat16 smb[];
    __nv_bfloat16* Ah = smb;
    __nv_bfloat16* Al = Ah + 128 * APADB;
    __nv_bfloat16* Bh = Al + 128 * APADB;
    __nv_bfloat16* Bl = Bh + 128 * APADB;

    int m0 = blockIdx.x * 128;
    int tid = threadIdx.x;
    int lane = tid & 31;
    int wid = tid >> 5;
    int wm = wid & 1;
    int wn = wid >> 1;

    uint32_t aAh = smem_u32(Ah), aAl = smem_u32(Al);
    uint32_t aBh = smem_u32(Bh), aBl = smem_u32(Bl);

    int lrow = (lane & 7) + ((lane >> 3) & 1) * 8;
    int lkoff = (lane >> 4) * 8;
    uint32_t baseA = (uint32_t)((wm * 64 + lrow) * APADB + lkoff) * 2;
    uint32_t baseB = (uint32_t)((wn * 32 + lrow) * APADB + lkoff) * 2;

    float acc[4][4][4];
#pragma unroll
    for (int a = 0; a < 4; ++a)
#pragma unroll
        for (int b = 0; b < 4; ++b)
#pragma unroll
            for (int cc = 0; cc < 4; ++cc) acc[a][b][cc] = 0.f;

    const uint4 zero4 = make_uint4(0u, 0u, 0u, 0u);
    int u4 = tid & 7;
    int rb = tid >> 3;

#pragma unroll 1
    for (int kc = 0; kc < KS; kc += 64) {
#pragma unroll
        for (int it = 0; it < 4; ++it) {
            int row = rb + it * 32;
            uint4 vh = zero4, vl = zero4;
            if (m0 + row < n) {
                size_t goff = (size_t)(m0 + row) * KS + kc + u4 * 8;
                vh = *(const uint4*)(g_agg_hi + goff);
                vl = *(const uint4*)(g_agg_lo + goff);
            }
            *(uint4*)(Ah + row * APADB + u4 * 8) = vh;
            *(uint4*)(Al + row * APADB + u4 * 8) = vl;
        }
#pragma unroll
        for (int it = 0; it < 4; ++it) {
            int nn = rb + it * 32;
            size_t goff = (size_t)nn * KS + kc + u4 * 8;
            *(uint4*)(Bh + nn * APADB + u4 * 8) = *(const uint4*)(g_wts_hi + goff);
            *(uint4*)(Bl + nn * APADB + u4 * 8) = *(const uint4*)(g_wts_lo + goff);
        }
        __syncthreads();

#pragma unroll
        for (int ks = 0; ks < 4; ++ks) {
            uint32_t koff = (uint32_t)(ks * 16) * 2;
            uint32_t ah[4][4], al[4][4], bh[4][2], bl[4][2];
#pragma unroll
            for (int mt = 0; mt < 4; ++mt) {
                ldsm_x4(ah[mt], aAh + baseA + koff + (uint32_t)(mt * 16 * APADB * 2));
                ldsm_x4(al[mt], aAl + baseA + koff + (uint32_t)(mt * 16 * APADB * 2));
            }
#pragma unroll
            for (int p = 0; p < 2; ++p) {
                uint32_t t4[4];
                ldsm_x4(t4, aBh + baseB + koff + (uint32_t)(p * 16 * APADB * 2));
                bh[2 * p][0] = t4[0]; bh[2 * p + 1][0] = t4[1];
                bh[2 * p][1] = t4[2]; bh[2 * p + 1][1] = t4[3];
                ldsm_x4(t4, aBl + baseB + koff + (uint32_t)(p * 16 * APADB * 2));
                bl[2 * p][0] = t4[0]; bl[2 * p + 1][0] = t4[1];
                bl[2 * p][1] = t4[2]; bl[2 * p + 1][1] = t4[3];
            }
#pragma unroll
            for (int mt = 0; mt < 4; ++mt)
#pragma unroll
                for (int nt = 0; nt < 4; ++nt) mma_bf16(acc[mt][nt], ah[mt], bh[nt]);
#pragma unroll
            for (int mt = 0; mt < 4; ++mt)
#pragma unroll
                for (int nt = 0; nt < 4; ++nt) mma_bf16(acc[mt][nt], ah[mt], bl[nt]);
#pragma unroll
            for (int mt = 0; mt < 4; ++mt)
#pragma unroll
                for (int nt = 0; nt < 4; ++nt) mma_bf16(acc[mt][nt], al[mt], bh[nt]);
        }
        __syncthreads();
    }

    float bx[4][2];
#pragma unroll
    for (int nt = 0; nt < 4; ++nt) {
        int col = wn * 32 + nt * 8 + 2 * (lane & 3);
        bx[nt][0] = bias[col];
        bx[nt][1] = bias[col + 1];
    }
#pragma unroll
    for (int mt = 0; mt < 4; ++mt) {
        int row0 = m0 + wm * 64 + mt * 16 + (lane >> 2);
        int row1 = row0 + 8;
#pragma unroll
        for (int nt = 0; nt < 4; ++nt) {
            int col = wn * 32 + nt * 8 + 2 * (lane & 3);
            float2 o0 = make_float2(acc[mt][nt][0] + bx[nt][0], acc[mt][nt][1] + bx[nt][1]);
            float2 o1 = make_float2(acc[mt][nt][2] + bx[nt][0], acc[mt][nt][3] + bx[nt][1]);
            if (relu) {
                o0.x = fmaxf(o0.x, 0.f); o0.y = fmaxf(o0.y, 0.f);
                o1.x = fmaxf(o1.x, 0.f); o1.y = fmaxf(o1.y, 0.f);
            }
            if (row0 < n) *(float2*)(out + (size_t)row0 * C + col) = o0;
            if (row1 < n) *(float2*)(out + (size_t)row1 * C + col) = o1;
        }
    }
}

// ---------------- driver ----------------
extern "C" void kernel_launch(void* const* d_in, const int* in_sizes, int n_in,
                              void* d_out, int out_size) {
    const float* x    = (const float*)d_in[0];
    const int*   ei   = (const int*)d_in[1];
    const int*   et   = (const int*)d_in[2];
    const float* attr = (const float*)d_in[3];
    const float *w1 = (const float*)d_in[4],  *q1 = (const float*)d_in[5],
                *k1 = (const float*)d_in[6],  *le1 = (const float*)d_in[7],
                *e1 = (const float*)d_in[8],  *b1 = (const float*)d_in[9];
    const float *w2 = (const float*)d_in[10], *q2 = (const float*)d_in[11],
                *k2 = (const float*)d_in[12], *le2 = (const float*)d_in[13],
                *e2 = (const float*)d_in[14], *b2 = (const float*)d_in[15];

    int n = in_sizes[0] / C;
    int e_cnt = in_sizes[2];
    const int* src = ei;
    const int* dst = ei + e_cnt;

    float* h = nullptr;
    cudaGetSymbolAddress((void**)&h, g_h);

    static bool attr_set = false;
    if (!attr_set) {
        cudaFuncSetAttribute(k_gemm_st, cudaFuncAttributeMaxDynamicSharedMemorySize, GEMM_SMEM);
        attr_set = true;
    }

    int nblk = (n + 1023) / 1024;
    int prep_grid = 2 * RELS + (RELS * C + 1 + 7) / 8;
    int gemm_grid = (n + 127) / 128;

    // CSR build + one-time edge scatter (pack + attr in CSR order)
    k_count<<<(e_cnt + 255) / 256, 256>>>(dst, e_cnt);
    k_scanA<<<nblk, 1024>>>(n);
    k_scanC<<<nblk, 1024>>>(n, nblk);
    k_fill<<<(e_cnt + 255) / 256, 256>>>(src, dst, et, attr, e_cnt);

    // layer 1
    k_prepall<<<prep_grid, 256>>>(w1, q1, k1, le1, e1);
    k_sqk<<<(n + 7) / 8, 256>>>(x, n);
    k_agg<<<(n + 7) / 8, 256>>>(x, n);
    k_gemm_st<<<gemm_grid, 256, GEMM_SMEM>>>(b1, h, 1, n);

    // layer 2
    k_prepall<<<prep_grid, 256>>>(w2, q2, k2, le2, e2);
    k_sqk<<<(n + 7) / 8, 256>>>(h, n);
    k_agg<<<(n + 7) / 8, 256>>>(h, n);
    k_gemm_st<<<gemm_grid, 256, GEMM_SMEM>>>(b2, (float*)d_out, 0, n);
}

// round 13
// speedup vs baseline: 1.0625x; 1.0619x over previous
#include <cuda_runtime.h>
#include <cuda_bf16.h>
#include <math_constants.h>
#include <cstdint>

#define MAXN 50000
#define MAXE 500000
#define C    128
#define RELS 3
#define KS   (RELS * C)   // 384 stacked K

// ---------------- scratch (static device memory; no allocation) ----------------
__device__ __align__(16) __nv_bfloat16 g_agg_hi[(size_t)MAXN * KS];
__device__ __align__(16) __nv_bfloat16 g_agg_lo[(size_t)MAXN * KS];
__device__ __align__(16) float g_h[(size_t)MAXN * C];
__device__ unsigned g_pack[MAXE];    // (r<<28)|src in CSR order (built once)
__device__ int      g_dstc[MAXE];    // dst in CSR order
__device__ float    g_attrc[MAXE];   // edge_attr in CSR order
__device__ float    g_alphac[MAXE];  // per-layer alpha in CSR order
__device__ float g_sq[RELS * MAXN];
__device__ float g_sk[RELS * MAXN];
__device__ __align__(16) float g_wq[RELS * C];
__device__ __align__(16) float g_wk[RELS * C];
__device__ float g_cattr;
__device__ __align__(16) __nv_bfloat16 g_wts_hi[C * KS];
__device__ __align__(16) __nv_bfloat16 g_wts_lo[C * KS];
__device__ int g_deg[MAXN];          // zero-init; re-zeroed by k_scanC each replay
__device__ int g_incl[MAXN];
__device__ int g_indptr[MAXN + 1];
__device__ int g_cursor[MAXN];
__device__ int g_bsum[64];

__device__ __forceinline__ uint32_t smem_u32(const void* p) {
    uint32_t a;
    asm("{ .reg .u64 t; cvta.to.shared.u64 t, %1; cvt.u32.u64 %0, t; }" : "=r"(a) : "l"(p));
    return a;
}
__device__ __forceinline__ void mma_bf16(float* c, const uint32_t* a, const uint32_t* b) {
    asm volatile(
        "mma.sync.aligned.m16n8k16.row.col.f32.bf16.bf16.f32 "
        "{%0,%1,%2,%3}, {%4,%5,%6,%7}, {%8,%9}, {%0,%1,%2,%3};"
        : "+f"(c[0]), "+f"(c[1]), "+f"(c[2]), "+f"(c[3])
        : "r"(a[0]), "r"(a[1]), "r"(a[2]), "r"(a[3]), "r"(b[0]), "r"(b[1]));
}
__device__ __forceinline__ void ldsm_x4(uint32_t* r, uint32_t addr) {
    asm volatile("ldmatrix.sync.aligned.m8n8.x4.shared.b16 {%0,%1,%2,%3}, [%4];"
                 : "=r"(r[0]), "=r"(r[1]), "=r"(r[2]), "=r"(r[3]) : "r"(addr));
}
__device__ __forceinline__ void store_split(__nv_bfloat16* hp, __nv_bfloat16* lp, float4 a) {
    __nv_bfloat16 h0 = __float2bfloat16(a.x), h1 = __float2bfloat16(a.y);
    __nv_bfloat16 h2 = __float2bfloat16(a.z), h3 = __float2bfloat16(a.w);
    __nv_bfloat162 hh0(h0, h1), hh1(h2, h3);
    __nv_bfloat162 ll0(__float2bfloat16(a.x - __bfloat162float(h0)),
                       __float2bfloat16(a.y - __bfloat162float(h1)));
    __nv_bfloat162 ll1(__float2bfloat16(a.z - __bfloat162float(h2)),
                       __float2bfloat16(a.w - __bfloat162float(h3)));
    ((__nv_bfloat162*)hp)[0] = hh0; ((__nv_bfloat162*)hp)[1] = hh1;
    ((__nv_bfloat162*)lp)[0] = ll0; ((__nv_bfloat162*)lp)[1] = ll1;
}
#define CP_ASYNC16(dst, src) asm volatile("cp.async.cg.shared.global [%0], [%1], 16;" :: "r"(dst), "l"(src))
#define CP_COMMIT()          asm volatile("cp.async.commit_group;")
#define CP_WAIT1()           asm volatile("cp.async.wait_group 1;")
#define CP_WAIT0()           asm volatile("cp.async.wait_group 0;")

// ---------------- CSR build ----------------
__global__ void k_count(const int* __restrict__ dst, int e_cnt) {
    int e = blockIdx.x * blockDim.x + threadIdx.x;
    if (e < e_cnt) atomicAdd(&g_deg[dst[e]], 1);
}
__global__ void k_scanA(int n) {
    __shared__ int sh[2][1024];
    int tid = threadIdx.x;
    int i = blockIdx.x * 1024 + tid;
    int v = (i < n) ? g_deg[i] : 0;
    sh[0][tid] = v;
    __syncthreads();
    int pb = 0;
#pragma unroll
    for (int off = 1; off < 1024; off <<= 1) {
        int nb = pb ^ 1;
        int val = sh[pb][tid];
        if (tid >= off) val += sh[pb][tid - off];
        sh[nb][tid] = val;
        pb = nb;
        __syncthreads();
    }
    int incl = sh[pb][tid];
    if (i < n) g_incl[i] = incl;
    if (tid == 1023) g_bsum[blockIdx.x] = incl;
}
__global__ void k_scanC(int n, int nblk) {
    __shared__ int sb[64];
    int tid = threadIdx.x;
    int bid = blockIdx.x;
    if (tid < 64) sb[tid] = (tid < nblk) ? g_bsum[tid] : 0;
    __syncthreads();
#pragma unroll
    for (int off = 1; off < 64; off <<= 1) {
        int add = (tid < 64 && tid >= off) ? sb[tid - off] : 0;
        __syncthreads();
        if (tid < 64) sb[tid] += add;
        __syncthreads();
    }
    int base = (bid == 0) ? 0 : sb[bid - 1];
    int i = bid * 1024 + tid;
    if (i < n) {
        int total = g_incl[i] + base;
        g_indptr[i + 1] = total;
        g_cursor[i] = total - g_deg[i];
        g_deg[i] = 0;
        if (i == 0) g_indptr[0] = 0;
    }
}
// one-time scatter: pack + attr + dst into CSR slots
__global__ void k_fill(const int* __restrict__ src, const int* __restrict__ dst,
                       const int* __restrict__ etype, const float* __restrict__ attr,
                       int e_cnt) {
    int e = blockIdx.x * blockDim.x + threadIdx.x;
    if (e >= e_cnt) return;
    int d = dst[e];
    int pos = atomicAdd(&g_cursor[d], 1);
    g_pack[pos] = (unsigned)src[e] | ((unsigned)etype[e] << 28);
    g_attrc[pos] = attr[e];
    g_dstc[pos] = d;
}

// ---------------- per-layer precompute (tiled W transpose-split + wq/wk/cattr) ----------------
__global__ void k_prepall(const float* __restrict__ w, const float* __restrict__ q,
                          const float* __restrict__ kk, const float* __restrict__ le,
                          const float* __restrict__ ee) {
    if (blockIdx.x < 2 * RELS) {
        __shared__ float tile[64][129];
        int r = blockIdx.x >> 1;
        int kt = (blockIdx.x & 1) * 64;
        const float* Wr = w + (size_t)r * C * C;
        int tid = threadIdx.x;
#pragma unroll
        for (int it = 0; it < 8; ++it) {
            int idx = tid + it * 256;
            int kkr = idx >> 5;
            int nn4 = (idx & 31) * 4;
            float4 v = *(const float4*)(Wr + (size_t)(kt + kkr) * C + nn4);
            tile[kkr][nn4] = v.x; tile[kkr][nn4 + 1] = v.y;
            tile[kkr][nn4 + 2] = v.z; tile[kkr][nn4 + 3] = v.w;
        }
        __syncthreads();
        int lane = tid & 31, wid = tid >> 5;
        for (int nn = wid; nn < C; nn += 8) {
            float v0 = tile[2 * lane][nn];
            float v1 = tile[2 * lane + 1][nn];
            __nv_bfloat16 h0 = __float2bfloat16(v0), h1 = __float2bfloat16(v1);
            __nv_bfloat162 hh(h0, h1);
            __nv_bfloat162 ll(__float2bfloat16(v0 - __bfloat162float(h0)),
                              __float2bfloat16(v1 - __bfloat162float(h1)));
            size_t off = (size_t)nn * KS + r * C + kt + 2 * lane;
            *(__nv_bfloat162*)(g_wts_hi + off) = hh;
            *(__nv_bfloat162*)(g_wts_lo + off) = ll;
        }
        return;
    }
    int gw = (blockIdx.x - 2 * RELS) * 8 + (threadIdx.x >> 5);
    int lane = threadIdx.x & 31;
    if (gw < RELS * C) {
        const float4* row = (const float4*)(w + (size_t)gw * C);
        float4 wv = row[lane];
        float4 qv = ((const float4*)q)[lane];
        float4 kv = ((const float4*)kk)[lane];
        float aq = wv.x * qv.x + wv.y * qv.y + wv.z * qv.z + wv.w * qv.w;
        float ak = wv.x * kv.x + wv.y * kv.y + wv.z * kv.z + wv.w * kv.w;
#pragma unroll
        for (int off = 16; off; off >>= 1) {
            aq += __shfl_xor_sync(0xffffffffu, aq, off);
            ak += __shfl_xor_sync(0xffffffffu, ak, off);
        }
        if (lane == 0) { g_wq[gw] = aq; g_wk[gw] = ak; }
    } else if (gw == RELS * C) {
        float p = 0.f;
        for (int o = lane; o < C; o += 32) p += le[o] * ee[o];
#pragma unroll
        for (int off = 16; off; off >>= 1) p += __shfl_xor_sync(0xffffffffu, p, off);
        if (lane == 0) g_cattr = p;
    }
}

// ---------------- per-node attention scalars ----------------
__global__ void k_sqk(const float* __restrict__ x, int n) {
    int gw = (blockIdx.x * blockDim.x + threadIdx.x) >> 5;
    int lane = threadIdx.x & 31;
    if (gw >= n) return;
    float4 xv = ((const float4*)x)[(size_t)gw * 32 + lane];
    float aq[RELS], ak[RELS];
#pragma unroll
    for (int r = 0; r < RELS; ++r) {
        float4 wqv = ((const float4*)g_wq)[r * 32 + lane];
        float4 wkv = ((const float4*)g_wk)[r * 32 + lane];
        aq[r] = xv.x * wqv.x + xv.y * wqv.y + xv.z * wqv.z + xv.w * wqv.w;
        ak[r] = xv.x * wkv.x + xv.y * wkv.y + xv.z * wkv.z + xv.w * wkv.w;
    }
#pragma unroll
    for (int off = 16; off; off >>= 1) {
#pragma unroll
        for (int r = 0; r < RELS; ++r) {
            aq[r] += __shfl_xor_sync(0xffffffffu, aq[r], off);
            ak[r] += __shfl_xor_sync(0xffffffffu, ak[r], off);
        }
    }
    if (lane == 0) {
#pragma unroll
        for (int r = 0; r < RELS; ++r) {
            g_sq[r * n + gw] = aq[r];
            g_sk[r * n + gw] = ak[r];
        }
    }
}

// ---------------- per-layer: alpha in CSR order (coalesced, no atomics) ----------------
__global__ void k_alphac(int n, int e_cnt) {
    int pos = blockIdx.x * blockDim.x + threadIdx.x;
    if (pos >= e_cnt) return;
    unsigned p = g_pack[pos];
    unsigned sv = p & 0x0FFFFFFFu, r = p >> 28;
    int d = g_dstc[pos];
    float a = g_sq[r * n + d] + g_sk[r * n + sv] + g_cattr * g_attrc[pos];
    g_alphac[pos] = (a > 0.f) ? a : 0.2f * a;
}

// ---------------- per-node softmax + aggregate raw x -> bf16-split g_agg ----------------
#define ACCUM(rr, co, v)                                                     \
    do {                                                                     \
        if ((rr) == 0) {                                                     \
            a0.x = fmaf(co, (v).x, a0.x); a0.y = fmaf(co, (v).y, a0.y);      \
            a0.z = fmaf(co, (v).z, a0.z); a0.w = fmaf(co, (v).w, a0.w);      \
        } else if ((rr) == 1) {                                              \
            a1.x = fmaf(co, (v).x, a1.x); a1.y = fmaf(co, (v).y, a1.y);      \
            a1.z = fmaf(co, (v).z, a1.z); a1.w = fmaf(co, (v).w, a1.w);      \
        } else {                                                             \
            a2.x = fmaf(co, (v).x, a2.x); a2.y = fmaf(co, (v).y, a2.y);      \
            a2.z = fmaf(co, (v).z, a2.z); a2.w = fmaf(co, (v).w, a2.w);      \
        }                                                                    \
    } while (0)

__global__ void k_agg(const float* __restrict__ xin, int n) {
    int gw = (blockIdx.x * blockDim.x + threadIdx.x) >> 5;
    int lane = threadIdx.x & 31;
    if (gw >= n) return;
    int beg = g_indptr[gw], end = g_indptr[gw + 1];

    float m = -CUDART_INF_F;
    for (int j = beg + lane; j < end; j += 32) m = fmaxf(m, g_alphac[j]);
#pragma unroll
    for (int off = 16; off; off >>= 1) m = fmaxf(m, __shfl_xor_sync(0xffffffffu, m, off));

    float s = 0.f;
    for (int j = beg + lane; j < end; j += 32) s += __expf(g_alphac[j] - m);
#pragma unroll
    for (int off = 16; off; off >>= 1) s += __shfl_xor_sync(0xffffffffu, s, off);
    float inv = 1.f / (s + 1e-16f);

    float4 a0 = make_float4(0.f, 0.f, 0.f, 0.f);
    float4 a1 = a0, a2 = a0;
    int j = beg;
    for (; j + 1 < end; j += 2) {
        float al0 = g_alphac[j], al1 = g_alphac[j + 1];
        unsigned p0 = g_pack[j], p1 = g_pack[j + 1];
        float4 v0 = ((const float4*)(xin + (size_t)(p0 & 0x0FFFFFFFu) * C))[lane];
        float4 v1 = ((const float4*)(xin + (size_t)(p1 & 0x0FFFFFFFu) * C))[lane];
        float c0 = __expf(al0 - m) * inv;
        float c1 = __expf(al1 - m) * inv;
        unsigned r0 = p0 >> 28, r1 = p1 >> 28;
        ACCUM(r0, c0, v0);
        ACCUM(r1, c1, v1);
    }
    if (j < end) {
        float al0 = g_alphac[j];
        unsigned p0 = g_pack[j];
        float4 v0 = ((const float4*)(xin + (size_t)(p0 & 0x0FFFFFFFu) * C))[lane];
        float c0 = __expf(al0 - m) * inv;
        unsigned r0 = p0 >> 28;
        ACCUM(r0, c0, v0);
    }
    size_t ob = (size_t)gw * KS + (size_t)lane * 4;
    store_split(g_agg_hi + ob,         g_agg_lo + ob,         a0);
    store_split(g_agg_hi + ob + C,     g_agg_lo + ob + C,     a1);
    store_split(g_agg_hi + ob + 2 * C, g_agg_lo + ob + 2 * C, a2);
}

// ---------------- stacked HMMA bf16 3-term GEMM, cp.async double-buffered ----------------
// tile M=128 x N=128, K=384 in 12 chunks of 32. 2 stages x 40KB smem. 2 CTAs/SM.
#define KC 32
#define NCH (KS / KC)       // 12
#define AST 40              // smem row stride (bf16 el): 5x16B groups, 5 coprime 8
#define STAGE_B 40960       // bytes per stage (4 arrays x 128 x 40 x 2)
#define ARR_B 10240
#define GEMM_SMEM (2 * STAGE_B)

__global__ __launch_bounds__(256, 2) void k_gemm_st(const float* __restrict__ bias,
                                                    float* __restrict__ out,
                                                    int relu, int n) {
    extern __shared__ __nv_bfloat16 smb[];
    uint32_t smemu = smem_u32(smb);

    int m0 = blockIdx.x * 128;
    int tid = threadIdx.x;
    int lane = tid & 31;
    int wid = tid >> 5;
    int wm = wid & 1;
    int wn = wid >> 1;

    int lrow = (lane & 7) + ((lane >> 3) & 1) * 8;
    int lkoff = (lane >> 4) * 8;
    uint32_t baseA = (uint32_t)((wm * 64 + lrow) * AST + lkoff) * 2;
    uint32_t baseB = (uint32_t)((wn * 32 + lrow) * AST + lkoff) * 2;

    float acc[4][4][4];
#pragma unroll
    for (int a = 0; a < 4; ++a)
#pragma unroll
        for (int b = 0; b < 4; ++b)
#pragma unroll
            for (int cc = 0; cc < 4; ++cc) acc[a][b][cc] = 0.f;

    int u = tid & 3;            // 16B group within 64B k-slice
    int row2 = tid >> 2;        // 0..63

    // chunk loader: issues 8 cp.async (A hi/lo + B hi/lo, 2 row-groups each)
    auto load_chunk = [&](int c, int st) {
        int kc = c * KC;
        uint32_t sb = smemu + (uint32_t)st * STAGE_B;
#pragma unroll
        for (int it = 0; it < 2; ++it) {
            int row = row2 + it * 64;
            uint32_t doff = (uint32_t)(row * 80 + u * 16);
            if (m0 + row < n) {
                size_t g = (size_t)(m0 + row) * KS + kc + u * 8;
                CP_ASYNC16(sb + doff, g_agg_hi + g);
                CP_ASYNC16(sb + ARR_B + doff, g_agg_lo + g);
            } else {
                *(uint4*)((char*)smb + st * STAGE_B + doff) = make_uint4(0u, 0u, 0u, 0u);
                *(uint4*)((char*)smb + st * STAGE_B + ARR_B + doff) = make_uint4(0u, 0u, 0u, 0u);
            }
            size_t gb = (size_t)row * KS + kc + u * 8;
            CP_ASYNC16(sb + 2 * ARR_B + doff, g_wts_hi + gb);
            CP_ASYNC16(sb + 3 * ARR_B + doff, g_wts_lo + gb);
        }
    };

    load_chunk(0, 0);
    CP_COMMIT();

#pragma unroll 1
    for (int c = 0; c < NCH; ++c) {
        int st = c & 1;
        if (c + 1 < NCH) {
            load_chunk(c + 1, st ^ 1);
            CP_COMMIT();
            CP_WAIT1();
        } else {
            CP_WAIT0();
        }
        __syncthreads();

        uint32_t sA = smemu + (uint32_t)st * STAGE_B;
        uint32_t sAl = sA + ARR_B, sBh = sA + 2 * ARR_B, sBl = sA + 3 * ARR_B;
#pragma unroll
        for (int ks = 0; ks < 2; ++ks) {
            uint32_t koff = (uint32_t)(ks * 16) * 2;
            uint32_t ah[4][4], al[4][4], bh[4][2], bl[4][2];
#pragma unroll
            for (int mt = 0; mt < 4; ++mt) {
                ldsm_x4(ah[mt], sA + baseA + koff + (uint32_t)(mt * 16 * AST * 2));
                ldsm_x4(al[mt], sAl + baseA + koff + (uint32_t)(mt * 16 * AST * 2));
            }
#pragma unroll
            for (int p = 0; p < 2; ++p) {
                uint32_t t4[4];
                ldsm_x4(t4, sBh + baseB + koff + (uint32_t)(p * 16 * AST * 2));
                bh[2 * p][0] = t4[0]; bh[2 * p + 1][0] = t4[1];
                bh[2 * p][1] = t4[2]; bh[2 * p + 1][1] = t4[3];
                ldsm_x4(t4, sBl + baseB + koff + (uint32_t)(p * 16 * AST * 2));
                bl[2 * p][0] = t4[0]; bl[2 * p + 1][0] = t4[1];
                bl[2 * p][1] = t4[2]; bl[2 * p + 1][1] = t4[3];
            }
#pragma unroll
            for (int mt = 0; mt < 4; ++mt)
#pragma unroll
                for (int nt = 0; nt < 4; ++nt) mma_bf16(acc[mt][nt], ah[mt], bh[nt]);
#pragma unroll
            for (int mt = 0; mt < 4; ++mt)
#pragma unroll
                for (int nt = 0; nt < 4; ++nt) mma_bf16(acc[mt][nt], ah[mt], bl[nt]);
#pragma unroll
            for (int mt = 0; mt < 4; ++mt)
#pragma unroll
                for (int nt = 0; nt < 4; ++nt) mma_bf16(acc[mt][nt], al[mt], bh[nt]);
        }
        __syncthreads();
    }

    float bx[4][2];
#pragma unroll
    for (int nt = 0; nt < 4; ++nt) {
        int col = wn * 32 + nt * 8 + 2 * (lane & 3);
        bx[nt][0] = bias[col];
        bx[nt][1] = bias[col + 1];
    }
#pragma unroll
    for (int mt = 0; mt < 4; ++mt) {
        int row0 = m0 + wm * 64 + mt * 16 + (lane >> 2);
        int row1 = row0 + 8;
#pragma unroll
        for (int nt = 0; nt < 4; ++nt) {
            int col = wn * 32 + nt * 8 + 2 * (lane & 3);
            float2 o0 = make_float2(acc[mt][nt][0] + bx[nt][0], acc[mt][nt][1] + bx[nt][1]);
            float2 o1 = make_float2(acc[mt][nt][2] + bx[nt][0], acc[mt][nt][3] + bx[nt][1]);
            if (relu) {
                o0.x = fmaxf(o0.x, 0.f); o0.y = fmaxf(o0.y, 0.f);
                o1.x = fmaxf(o1.x, 0.f); o1.y = fmaxf(o1.y, 0.f);
            }
            if (row0 < n) *(float2*)(out + (size_t)row0 * C + col) = o0;
            if (row1 < n) *(float2*)(out + (size_t)row1 * C + col) = o1;
        }
    }
}

// ---------------- driver ----------------
extern "C" void kernel_launch(void* const* d_in, const int* in_sizes, int n_in,
                              void* d_out, int out_size) {
    const float* x    = (const float*)d_in[0];
    const int*   ei   = (const int*)d_in[1];
    const int*   et   = (const int*)d_in[2];
    const float* attr = (const float*)d_in[3];
    const float *w1 = (const float*)d_in[4],  *q1 = (const float*)d_in[5],
                *k1 = (const float*)d_in[6],  *le1 = (const float*)d_in[7],
                *e1 = (const float*)d_in[8],  *b1 = (const float*)d_in[9];
    const float *w2 = (const float*)d_in[10], *q2 = (const float*)d_in[11],
                *k2 = (const float*)d_in[12], *le2 = (const float*)d_in[13],
                *e2 = (const float*)d_in[14], *b2 = (const float*)d_in[15];

    int n = in_sizes[0] / C;
    int e_cnt = in_sizes[2];
    const int* src = ei;
    const int* dst = ei + e_cnt;

    float* h = nullptr;
    cudaGetSymbolAddress((void**)&h, g_h);

    static bool attr_set = false;
    if (!attr_set) {
        cudaFuncSetAttribute(k_gemm_st, cudaFuncAttributeMaxDynamicSharedMemorySize, GEMM_SMEM);
        attr_set = true;
    }

    int nblk = (n + 1023) / 1024;
    int prep_grid = 2 * RELS + (RELS * C + 1 + 7) / 8;
    int gemm_grid = (n + 127) / 128;
    int eb = (e_cnt + 255) / 256;

    // CSR build + one-time edge scatter
    k_count<<<eb, 256>>>(dst, e_cnt);
    k_scanA<<<nblk, 1024>>>(n);
    k_scanC<<<nblk, 1024>>>(n, nblk);
    k_fill<<<eb, 256>>>(src, dst, et, attr, e_cnt);

    // layer 1
    k_prepall<<<prep_grid, 256>>>(w1, q1, k1, le1, e1);
    k_sqk<<<(n + 7) / 8, 256>>>(x, n);
    k_alphac<<<eb, 256>>>(n, e_cnt);
    k_agg<<<(n + 7) / 8, 256>>>(x, n);
    k_gemm_st<<<gemm_grid, 256, GEMM_SMEM>>>(b1, h, 1, n);

    // layer 2
    k_prepall<<<prep_grid, 256>>>(w2, q2, k2, le2, e2);
    k_sqk<<<(n + 7) / 8, 256>>>(h, n);
    k_alphac<<<eb, 256>>>(n, e_cnt);
    k_agg<<<(n + 7) / 8, 256>>>(h, n);
    k_gemm_st<<<gemm_grid, 256, GEMM_SMEM>>>(b2, (float*)d_out, 0, n);
}

// round 14
// speedup vs baseline: 1.0764x; 1.0131x over previous
#include <cuda_runtime.h>
#include <cuda_bf16.h>
#include <math_constants.h>
#include <cstdint>

#define MAXN 50000
#define MAXE 500000
#define C    128
#define RELS 3
#define KS   (RELS * C)   // 384 stacked K

// ---------------- scratch (static device memory; no allocation) ----------------
__device__ __align__(16) __nv_bfloat16 g_agg_hi[(size_t)MAXN * KS];
__device__ __align__(16) __nv_bfloat16 g_agg_lo[(size_t)MAXN * KS];
__device__ __align__(16) float g_h[(size_t)MAXN * C];
__device__ unsigned g_pack[MAXE];    // (r<<28)|src in CSR order (built once)
__device__ int      g_dstc[MAXE];    // dst in CSR order
__device__ float    g_attrc[MAXE];   // edge_attr in CSR order
__device__ float    g_alphac[MAXE];  // per-layer alpha in CSR order
__device__ float g_sq[RELS * MAXN];
__device__ float g_sk[RELS * MAXN];
__device__ __align__(16) float g_wq[RELS * C];
__device__ __align__(16) float g_wk[RELS * C];
__device__ float g_cattr;
__device__ __align__(16) __nv_bfloat16 g_wts_hi[2ull * C * KS];  // double-buffered stacked W^T
__device__ __align__(16) __nv_bfloat16 g_wts_lo[2ull * C * KS];
__device__ int g_deg[MAXN];          // zero-init; re-zeroed by k_scanC each replay
__device__ int g_incl[MAXN];
__device__ int g_indptr[MAXN + 1];
__device__ int g_cursor[MAXN];
__device__ int g_bsum[64];

__device__ __forceinline__ uint32_t smem_u32(const void* p) {
    uint32_t a;
    asm("{ .reg .u64 t; cvta.to.shared.u64 t, %1; cvt.u32.u64 %0, t; }" : "=r"(a) : "l"(p));
    return a;
}
__device__ __forceinline__ void mma_bf16(float* c, const uint32_t* a, const uint32_t* b) {
    asm volatile(
        "mma.sync.aligned.m16n8k16.row.col.f32.bf16.bf16.f32 "
        "{%0,%1,%2,%3}, {%4,%5,%6,%7}, {%8,%9}, {%0,%1,%2,%3};"
        : "+f"(c[0]), "+f"(c[1]), "+f"(c[2]), "+f"(c[3])
        : "r"(a[0]), "r"(a[1]), "r"(a[2]), "r"(a[3]), "r"(b[0]), "r"(b[1]));
}
__device__ __forceinline__ void ldsm_x4(uint32_t* r, uint32_t addr) {
    asm volatile("ldmatrix.sync.aligned.m8n8.x4.shared.b16 {%0,%1,%2,%3}, [%4];"
                 : "=r"(r[0]), "=r"(r[1]), "=r"(r[2]), "=r"(r[3]) : "r"(addr));
}
__device__ __forceinline__ void store_split(__nv_bfloat16* hp, __nv_bfloat16* lp, float4 a) {
    __nv_bfloat16 h0 = __float2bfloat16(a.x), h1 = __float2bfloat16(a.y);
    __nv_bfloat16 h2 = __float2bfloat16(a.z), h3 = __float2bfloat16(a.w);
    __nv_bfloat162 hh0(h0, h1), hh1(h2, h3);
    __nv_bfloat162 ll0(__float2bfloat16(a.x - __bfloat162float(h0)),
                       __float2bfloat16(a.y - __bfloat162float(h1)));
    __nv_bfloat162 ll1(__float2bfloat16(a.z - __bfloat162float(h2)),
                       __float2bfloat16(a.w - __bfloat162float(h3)));
    ((__nv_bfloat162*)hp)[0] = hh0; ((__nv_bfloat162*)hp)[1] = hh1;
    ((__nv_bfloat162*)lp)[0] = ll0; ((__nv_bfloat162*)lp)[1] = ll1;
}
#define CP_ASYNC16(dst, src) asm volatile("cp.async.cg.shared.global [%0], [%1], 16;" :: "r"(dst), "l"(src))
#define CP_COMMIT()          asm volatile("cp.async.commit_group;")
#define CP_WAIT1()           asm volatile("cp.async.wait_group 1;")
#define CP_WAIT0()           asm volatile("cp.async.wait_group 0;")

#define PREP_GRID (2 * RELS + (RELS * C + 1 + 7) / 8)   // 55

// ---------------- device bodies ----------------
// prepall body: bid in [0, PREP_GRID). wbuf selects weight double-buffer.
__device__ void prepall_body(int bid, int wbuf,
                             const float* __restrict__ w, const float* __restrict__ q,
                             const float* __restrict__ kk, const float* __restrict__ le,
                             const float* __restrict__ ee, float* tile /*[64][129]*/) {
    __nv_bfloat16* wh = g_wts_hi + (size_t)wbuf * C * KS;
    __nv_bfloat16* wl = g_wts_lo + (size_t)wbuf * C * KS;
    if (bid < 2 * RELS) {
        int r = bid >> 1;
        int kt = (bid & 1) * 64;
        const float* Wr = w + (size_t)r * C * C;
        int tid = threadIdx.x;
#pragma unroll
        for (int it = 0; it < 8; ++it) {
            int idx = tid + it * 256;
            int kkr = idx >> 5;
            int nn4 = (idx & 31) * 4;
            float4 v = *(const float4*)(Wr + (size_t)(kt + kkr) * C + nn4);
            tile[kkr * 129 + nn4] = v.x; tile[kkr * 129 + nn4 + 1] = v.y;
            tile[kkr * 129 + nn4 + 2] = v.z; tile[kkr * 129 + nn4 + 3] = v.w;
        }
        __syncthreads();
        int lane = tid & 31, wid = tid >> 5;
        for (int nn = wid; nn < C; nn += 8) {
            float v0 = tile[(2 * lane) * 129 + nn];
            float v1 = tile[(2 * lane + 1) * 129 + nn];
            __nv_bfloat16 h0 = __float2bfloat16(v0), h1 = __float2bfloat16(v1);
            __nv_bfloat162 hh(h0, h1);
            __nv_bfloat162 ll(__float2bfloat16(v0 - __bfloat162float(h0)),
                              __float2bfloat16(v1 - __bfloat162float(h1)));
            size_t off = (size_t)nn * KS + r * C + kt + 2 * lane;
            *(__nv_bfloat162*)(wh + off) = hh;
            *(__nv_bfloat162*)(wl + off) = ll;
        }
        return;
    }
    int gw = (bid - 2 * RELS) * 8 + (threadIdx.x >> 5);
    int lane = threadIdx.x & 31;
    if (gw < RELS * C) {
        const float4* row = (const float4*)(w + (size_t)gw * C);
        float4 wv = row[lane];
        float4 qv = ((const float4*)q)[lane];
        float4 kv = ((const float4*)kk)[lane];
        float aq = wv.x * qv.x + wv.y * qv.y + wv.z * qv.z + wv.w * qv.w;
        float ak = wv.x * kv.x + wv.y * kv.y + wv.z * kv.z + wv.w * kv.w;
#pragma unroll
        for (int off = 16; off; off >>= 1) {
            aq += __shfl_xor_sync(0xffffffffu, aq, off);
            ak += __shfl_xor_sync(0xffffffffu, ak, off);
        }
        if (lane == 0) { g_wq[gw] = aq; g_wk[gw] = ak; }
    } else if (gw == RELS * C) {
        float p = 0.f;
        for (int o = lane; o < C; o += 32) p += le[o] * ee[o];
#pragma unroll
        for (int off = 16; off; off >>= 1) p += __shfl_xor_sync(0xffffffffu, p, off);
        if (lane == 0) g_cattr = p;
    }
}

__device__ void sqk_body(int gwarp, const float* __restrict__ x, int n) {
    int lane = threadIdx.x & 31;
    if (gwarp >= n) return;
    float4 xv = ((const float4*)x)[(size_t)gwarp * 32 + lane];
    float aq[RELS], ak[RELS];
#pragma unroll
    for (int r = 0; r < RELS; ++r) {
        float4 wqv = ((const float4*)g_wq)[r * 32 + lane];
        float4 wkv = ((const float4*)g_wk)[r * 32 + lane];
        aq[r] = xv.x * wqv.x + xv.y * wqv.y + xv.z * wqv.z + xv.w * wqv.w;
        ak[r] = xv.x * wkv.x + xv.y * wkv.y + xv.z * wkv.z + xv.w * wkv.w;
    }
#pragma unroll
    for (int off = 16; off; off >>= 1) {
#pragma unroll
        for (int r = 0; r < RELS; ++r) {
            aq[r] += __shfl_xor_sync(0xffffffffu, aq[r], off);
            ak[r] += __shfl_xor_sync(0xffffffffu, ak[r], off);
        }
    }
    if (lane == 0) {
#pragma unroll
        for (int r = 0; r < RELS; ++r) {
            g_sq[r * n + gwarp] = aq[r];
            g_sk[r * n + gwarp] = ak[r];
        }
    }
}

#define ACCUM(rr, co, v)                                                     \
    do {                                                                     \
        if ((rr) == 0) {                                                     \
            a0.x = fmaf(co, (v).x, a0.x); a0.y = fmaf(co, (v).y, a0.y);      \
            a0.z = fmaf(co, (v).z, a0.z); a0.w = fmaf(co, (v).w, a0.w);      \
        } else if ((rr) == 1) {                                              \
            a1.x = fmaf(co, (v).x, a1.x); a1.y = fmaf(co, (v).y, a1.y);      \
            a1.z = fmaf(co, (v).z, a1.z); a1.w = fmaf(co, (v).w, a1.w);      \
        } else {                                                             \
            a2.x = fmaf(co, (v).x, a2.x); a2.y = fmaf(co, (v).y, a2.y);      \
            a2.z = fmaf(co, (v).z, a2.z); a2.w = fmaf(co, (v).w, a2.w);      \
        }                                                                    \
    } while (0)

__device__ void agg_body(int gwarp, const float* __restrict__ xin, int n) {
    int lane = threadIdx.x & 31;
    if (gwarp >= n) return;
    int beg = g_indptr[gwarp], end = g_indptr[gwarp + 1];

    float m = -CUDART_INF_F;
    for (int j = beg + lane; j < end; j += 32) m = fmaxf(m, g_alphac[j]);
#pragma unroll
    for (int off = 16; off; off >>= 1) m = fmaxf(m, __shfl_xor_sync(0xffffffffu, m, off));

    float s = 0.f;
    for (int j = beg + lane; j < end; j += 32) s += __expf(g_alphac[j] - m);
#pragma unroll
    for (int off = 16; off; off >>= 1) s += __shfl_xor_sync(0xffffffffu, s, off);
    float inv = 1.f / (s + 1e-16f);

    float4 a0 = make_float4(0.f, 0.f, 0.f, 0.f);
    float4 a1 = a0, a2 = a0;
    int j = beg;
    for (; j + 1 < end; j += 2) {
        float al0 = g_alphac[j], al1 = g_alphac[j + 1];
        unsigned p0 = g_pack[j], p1 = g_pack[j + 1];
        float4 v0 = ((const float4*)(xin + (size_t)(p0 & 0x0FFFFFFFu) * C))[lane];
        float4 v1 = ((const float4*)(xin + (size_t)(p1 & 0x0FFFFFFFu) * C))[lane];
        float c0 = __expf(al0 - m) * inv;
        float c1 = __expf(al1 - m) * inv;
        unsigned r0 = p0 >> 28, r1 = p1 >> 28;
        ACCUM(r0, c0, v0);
        ACCUM(r1, c1, v1);
    }
    if (j < end) {
        float al0 = g_alphac[j];
        unsigned p0 = g_pack[j];
        float4 v0 = ((const float4*)(xin + (size_t)(p0 & 0x0FFFFFFFu) * C))[lane];
        float c0 = __expf(al0 - m) * inv;
        unsigned r0 = p0 >> 28;
        ACCUM(r0, c0, v0);
    }
    size_t ob = (size_t)gwarp * KS + (size_t)lane * 4;
    store_split(g_agg_hi + ob,         g_agg_lo + ob,         a0);
    store_split(g_agg_hi + ob + C,     g_agg_lo + ob + C,     a1);
    store_split(g_agg_hi + ob + 2 * C, g_agg_lo + ob + 2 * C, a2);
}

// ---------------- fused kernels ----------------
// launch 1: prepall(layer w, buf) blocks [0,PREP_GRID) ; count blocks after
__global__ void k_cnt_prep(const int* __restrict__ dst, int e_cnt,
                           const float* __restrict__ w, const float* __restrict__ q,
                           const float* __restrict__ kk, const float* __restrict__ le,
                           const float* __restrict__ ee, int wbuf) {
    __shared__ float tile[64 * 129];
    if (blockIdx.x < PREP_GRID) {
        prepall_body(blockIdx.x, wbuf, w, q, kk, le, ee, tile);
        return;
    }
    int e = (blockIdx.x - PREP_GRID) * blockDim.x + threadIdx.x;
    if (e < e_cnt) atomicAdd(&g_deg[dst[e]], 1);
}

__global__ void k_scanA(int n) {
    __shared__ int sh[2][1024];
    int tid = threadIdx.x;
    int i = blockIdx.x * 1024 + tid;
    int v = (i < n) ? g_deg[i] : 0;
    sh[0][tid] = v;
    __syncthreads();
    int pb = 0;
#pragma unroll
    for (int off = 1; off < 1024; off <<= 1) {
        int nb = pb ^ 1;
        int val = sh[pb][tid];
        if (tid >= off) val += sh[pb][tid - off];
        sh[nb][tid] = val;
        pb = nb;
        __syncthreads();
    }
    int incl = sh[pb][tid];
    if (i < n) g_incl[i] = incl;
    if (tid == 1023) g_bsum[blockIdx.x] = incl;
}
__global__ void k_scanC(int n, int nblk) {
    __shared__ int sb[64];
    int tid = threadIdx.x;
    int bid = blockIdx.x;
    if (tid < 64) sb[tid] = (tid < nblk) ? g_bsum[tid] : 0;
    __syncthreads();
#pragma unroll
    for (int off = 1; off < 64; off <<= 1) {
        int add = (tid < 64 && tid >= off) ? sb[tid - off] : 0;
        __syncthreads();
        if (tid < 64) sb[tid] += add;
        __syncthreads();
    }
    int base = (bid == 0) ? 0 : sb[bid - 1];
    int i = bid * 1024 + tid;
    if (i < n) {
        int total = g_incl[i] + base;
        g_indptr[i + 1] = total;
        g_cursor[i] = total - g_deg[i];
        g_deg[i] = 0;
        if (i == 0) g_indptr[0] = 0;
    }
}

// launch 4: sqk(layer1) blocks [0, sqk_grid) ; fill blocks after
__global__ void k_fill_sqk(const int* __restrict__ src, const int* __restrict__ dst,
                           const int* __restrict__ etype, const float* __restrict__ attr,
                           int e_cnt, const float* __restrict__ x, int n, int sqk_grid) {
    if ((int)blockIdx.x < sqk_grid) {
        int gwarp = blockIdx.x * 8 + (threadIdx.x >> 5);
        sqk_body(gwarp, x, n);
        return;
    }
    int e = (blockIdx.x - sqk_grid) * blockDim.x + threadIdx.x;
    if (e >= e_cnt) return;
    int d = dst[e];
    int pos = atomicAdd(&g_cursor[d], 1);
    g_pack[pos] = (unsigned)src[e] | ((unsigned)etype[e] << 28);
    g_attrc[pos] = attr[e];
    g_dstc[pos] = d;
}

__global__ void k_alphac(int n, int e_cnt) {
    int pos = blockIdx.x * blockDim.x + threadIdx.x;
    if (pos >= e_cnt) return;
    unsigned p = g_pack[pos];
    unsigned sv = p & 0x0FFFFFFFu, r = p >> 28;
    int d = g_dstc[pos];
    float a = g_sq[r * n + d] + g_sk[r * n + sv] + g_cattr * g_attrc[pos];
    g_alphac[pos] = (a > 0.f) ? a : 0.2f * a;
}

// launch 6: agg(layer1) blocks [0, agg_grid) ; prepall(layer2, buf1) blocks after
__global__ void k_agg_prep(const float* __restrict__ xin, int n, int agg_grid,
                           const float* __restrict__ w, const float* __restrict__ q,
                           const float* __restrict__ kk, const float* __restrict__ le,
                           const float* __restrict__ ee, int wbuf) {
    __shared__ float tile[64 * 129];
    if ((int)blockIdx.x >= agg_grid) {
        prepall_body(blockIdx.x - agg_grid, wbuf, w, q, kk, le, ee, tile);
        return;
    }
    int gwarp = blockIdx.x * 8 + (threadIdx.x >> 5);
    agg_body(gwarp, xin, n);
}

// plain variants for layer 2
__global__ void k_sqk(const float* __restrict__ x, int n) {
    int gwarp = blockIdx.x * 8 + (threadIdx.x >> 5);
    sqk_body(gwarp, x, n);
}
__global__ void k_agg(const float* __restrict__ xin, int n) {
    int gwarp = blockIdx.x * 8 + (threadIdx.x >> 5);
    agg_body(gwarp, xin, n);
}

// ---------------- stacked HMMA bf16 3-term GEMM, cp.async double-buffered ----------------
#define KC 32
#define NCH (KS / KC)       // 12
#define AST 40              // smem row stride (bf16 el)
#define STAGE_B 40960
#define ARR_B 10240
#define GEMM_SMEM (2 * STAGE_B)

__global__ __launch_bounds__(256, 2) void k_gemm_st(const float* __restrict__ bias,
                                                    float* __restrict__ out,
                                                    int relu, int n, int wbuf) {
    extern __shared__ __nv_bfloat16 smb[];
    uint32_t smemu = smem_u32(smb);
    const __nv_bfloat16* wth = g_wts_hi + (size_t)wbuf * C * KS;
    const __nv_bfloat16* wtl = g_wts_lo + (size_t)wbuf * C * KS;

    int m0 = blockIdx.x * 128;
    int tid = threadIdx.x;
    int lane = tid & 31;
    int wid = tid >> 5;
    int wm = wid & 1;
    int wn = wid >> 1;

    int lrow = (lane & 7) + ((lane >> 3) & 1) * 8;
    int lkoff = (lane >> 4) * 8;
    uint32_t baseA = (uint32_t)((wm * 64 + lrow) * AST + lkoff) * 2;
    uint32_t baseB = (uint32_t)((wn * 32 + lrow) * AST + lkoff) * 2;

    float acc[4][4][4];
#pragma unroll
    for (int a = 0; a < 4; ++a)
#pragma unroll
        for (int b = 0; b < 4; ++b)
#pragma unroll
            for (int cc = 0; cc < 4; ++cc) acc[a][b][cc] = 0.f;

    int u = tid & 3;
    int row2 = tid >> 2;

    auto load_chunk = [&](int c, int st) {
        int kc = c * KC;
        uint32_t sb = smemu + (uint32_t)st * STAGE_B;
#pragma unroll
        for (int it = 0; it < 2; ++it) {
            int row = row2 + it * 64;
            uint32_t doff = (uint32_t)(row * 80 + u * 16);
            if (m0 + row < n) {
                size_t g = (size_t)(m0 + row) * KS + kc + u * 8;
                CP_ASYNC16(sb + doff, g_agg_hi + g);
                CP_ASYNC16(sb + ARR_B + doff, g_agg_lo + g);
            } else {
                *(uint4*)((char*)smb + st * STAGE_B + doff) = make_uint4(0u, 0u, 0u, 0u);
                *(uint4*)((char*)smb + st * STAGE_B + ARR_B + doff) = make_uint4(0u, 0u, 0u, 0u);
            }
            size_t gb = (size_t)row * KS + kc + u * 8;
            CP_ASYNC16(sb + 2 * ARR_B + doff, wth + gb);
            CP_ASYNC16(sb + 3 * ARR_B + doff, wtl + gb);
        }
    };

    load_chunk(0, 0);
    CP_COMMIT();

#pragma unroll 1
    for (int c = 0; c < NCH; ++c) {
        int st = c & 1;
        if (c + 1 < NCH) {
            load_chunk(c + 1, st ^ 1);
            CP_COMMIT();
            CP_WAIT1();
        } else {
            CP_WAIT0();
        }
        __syncthreads();

        uint32_t sA = smemu + (uint32_t)st * STAGE_B;
        uint32_t sAl = sA + ARR_B, sBh = sA + 2 * ARR_B, sBl = sA + 3 * ARR_B;
#pragma unroll
        for (int ks = 0; ks < 2; ++ks) {
            uint32_t koff = (uint32_t)(ks * 16) * 2;
            uint32_t ah[4][4], al[4][4], bh[4][2], bl[4][2];
#pragma unroll
            for (int mt = 0; mt < 4; ++mt) {
                ldsm_x4(ah[mt], sA + baseA + koff + (uint32_t)(mt * 16 * AST * 2));
                ldsm_x4(al[mt], sAl + baseA + koff + (uint32_t)(mt * 16 * AST * 2));
            }
#pragma unroll
            for (int p = 0; p < 2; ++p) {
                uint32_t t4[4];
                ldsm_x4(t4, sBh + baseB + koff + (uint32_t)(p * 16 * AST * 2));
                bh[2 * p][0] = t4[0]; bh[2 * p + 1][0] = t4[1];
                bh[2 * p][1] = t4[2]; bh[2 * p + 1][1] = t4[3];
                ldsm_x4(t4, sBl + baseB + koff + (uint32_t)(p * 16 * AST * 2));
                bl[2 * p][0] = t4[0]; bl[2 * p + 1][0] = t4[1];
                bl[2 * p][1] = t4[2]; bl[2 * p + 1][1] = t4[3];
            }
#pragma unroll
            for (int mt = 0; mt < 4; ++mt)
#pragma unroll
                for (int nt = 0; nt < 4; ++nt) mma_bf16(acc[mt][nt], ah[mt], bh[nt]);
#pragma unroll
            for (int mt = 0; mt < 4; ++mt)
#pragma unroll
                for (int nt = 0; nt < 4; ++nt) mma_bf16(acc[mt][nt], ah[mt], bl[nt]);
#pragma unroll
            for (int mt = 0; mt < 4; ++mt)
#pragma unroll
                for (int nt = 0; nt < 4; ++nt) mma_bf16(acc[mt][nt], al[mt], bh[nt]);
        }
        __syncthreads();
    }

    float bx[4][2];
#pragma unroll
    for (int nt = 0; nt < 4; ++nt) {
        int col = wn * 32 + nt * 8 + 2 * (lane & 3);
        bx[nt][0] = bias[col];
        bx[nt][1] = bias[col + 1];
    }
#pragma unroll
    for (int mt = 0; mt < 4; ++mt) {
        int row0 = m0 + wm * 64 + mt * 16 + (lane >> 2);
        int row1 = row0 + 8;
#pragma unroll
        for (int nt = 0; nt < 4; ++nt) {
            int col = wn * 32 + nt * 8 + 2 * (lane & 3);
            float2 o0 = make_float2(acc[mt][nt][0] + bx[nt][0], acc[mt][nt][1] + bx[nt][1]);
            float2 o1 = make_float2(acc[mt][nt][2] + bx[nt][0], acc[mt][nt][3] + bx[nt][1]);
            if (relu) {
                o0.x = fmaxf(o0.x, 0.f); o0.y = fmaxf(o0.y, 0.f);
                o1.x = fmaxf(o1.x, 0.f); o1.y = fmaxf(o1.y, 0.f);
            }
            if (row0 < n) *(float2*)(out + (size_t)row0 * C + col) = o0;
            if (row1 < n) *(float2*)(out + (size_t)row1 * C + col) = o1;
        }
    }
}

// ---------------- driver ----------------
extern "C" void kernel_launch(void* const* d_in, const int* in_sizes, int n_in,
                              void* d_out, int out_size) {
    const float* x    = (const float*)d_in[0];
    const int*   ei   = (const int*)d_in[1];
    const int*   et   = (const int*)d_in[2];
    const float* attr = (const float*)d_in[3];
    const float *w1 = (const float*)d_in[4],  *q1 = (const float*)d_in[5],
                *k1 = (const float*)d_in[6],  *le1 = (const float*)d_in[7],
                *e1 = (const float*)d_in[8],  *b1 = (const float*)d_in[9];
    const float *w2 = (const float*)d_in[10], *q2 = (const float*)d_in[11],
                *k2 = (const float*)d_in[12], *le2 = (const float*)d_in[13],
                *e2 = (const float*)d_in[14], *b2 = (const float*)d_in[15];

    int n = in_sizes[0] / C;
    int e_cnt = in_sizes[2];
    const int* src = ei;
    const int* dst = ei + e_cnt;

    float* h = nullptr;
    cudaGetSymbolAddress((void**)&h, g_h);

    static bool attr_set = false;
    if (!attr_set) {
        cudaFuncSetAttribute(k_gemm_st, cudaFuncAttributeMaxDynamicSharedMemorySize, GEMM_SMEM);
        attr_set = true;
    }

    int nblk = (n + 1023) / 1024;
    int gemm_grid = (n + 127) / 128;
    int eb = (e_cnt + 255) / 256;
    int ng = (n + 7) / 8;

    // 1: prepall(L1, buf0) + count
    k_cnt_prep<<<PREP_GRID + eb, 256>>>(dst, e_cnt, w1, q1, k1, le1, e1, 0);
    // 2,3: scan
    k_scanA<<<nblk, 1024>>>(n);
    k_scanC<<<nblk, 1024>>>(n, nblk);
    // 4: sqk(L1) + fill
    k_fill_sqk<<<ng + eb, 256>>>(src, dst, et, attr, e_cnt, x, n, ng);
    // 5: alpha(L1)
    k_alphac<<<eb, 256>>>(n, e_cnt);
    // 6: agg(L1) + prepall(L2, buf1)
    k_agg_prep<<<ng + PREP_GRID, 256>>>(x, n, ng, w2, q2, k2, le2, e2, 1);
    // 7: gemm(L1, buf0)
    k_gemm_st<<<gemm_grid, 256, GEMM_SMEM>>>(b1, h, 1, n, 0);
    // 8-11: layer 2
    k_sqk<<<ng, 256>>>(h, n);
    k_alphac<<<eb, 256>>>(n, e_cnt);
    k_agg<<<ng, 256>>>(h, n);
    k_gemm_st<<<gemm_grid, 256, GEMM_SMEM>>>(b2, (float*)d_out, 0, n, 1);
}

// round 15
// speedup vs baseline: 1.1238x; 1.0440x over previous
#include <cuda_runtime.h>
#include <cuda_bf16.h>
#include <math_constants.h>
#include <cstdint>

#define MAXN 50000
#define MAXE 500000
#define C    128
#define RELS 3
#define KS   (RELS * C)   // 384 stacked K

// ---------------- scratch (static device memory; no allocation) ----------------
__device__ __align__(16) __nv_bfloat16 g_agg_hi[(size_t)MAXN * KS];
__device__ __align__(16) __nv_bfloat16 g_agg_lo[(size_t)MAXN * KS];
__device__ __align__(16) float g_h[(size_t)MAXN * C];
__device__ unsigned g_pack[MAXE];
__device__ int      g_dstc[MAXE];
__device__ float    g_attrc[MAXE];
__device__ float    g_alphac[MAXE];
__device__ float g_sq[RELS * MAXN];
__device__ float g_sk[RELS * MAXN];
__device__ __align__(16) float g_wq[RELS * C];
__device__ __align__(16) float g_wk[RELS * C];
__device__ float g_cattr;
__device__ __align__(16) __nv_bfloat16 g_wts_hi[2ull * C * KS];
__device__ __align__(16) __nv_bfloat16 g_wts_lo[2ull * C * KS];
__device__ int g_deg[MAXN];
__device__ int g_incl[MAXN];
__device__ int g_indptr[MAXN + 1];
__device__ int g_cursor[MAXN];
__device__ int g_bsum[64];

__device__ __forceinline__ uint32_t smem_u32(const void* p) {
    uint32_t a;
    asm("{ .reg .u64 t; cvta.to.shared.u64 t, %1; cvt.u32.u64 %0, t; }" : "=r"(a) : "l"(p));
    return a;
}
__device__ __forceinline__ void mma_bf16(float* c, const uint32_t* a, const uint32_t* b) {
    asm volatile(
        "mma.sync.aligned.m16n8k16.row.col.f32.bf16.bf16.f32 "
        "{%0,%1,%2,%3}, {%4,%5,%6,%7}, {%8,%9}, {%0,%1,%2,%3};"
        : "+f"(c[0]), "+f"(c[1]), "+f"(c[2]), "+f"(c[3])
        : "r"(a[0]), "r"(a[1]), "r"(a[2]), "r"(a[3]), "r"(b[0]), "r"(b[1]));
}
__device__ __forceinline__ void ldsm_x4(uint32_t* r, uint32_t addr) {
    asm volatile("ldmatrix.sync.aligned.m8n8.x4.shared.b16 {%0,%1,%2,%3}, [%4];"
                 : "=r"(r[0]), "=r"(r[1]), "=r"(r[2]), "=r"(r[3]) : "r"(addr));
}
__device__ __forceinline__ void store_split(__nv_bfloat16* hp, __nv_bfloat16* lp, float4 a) {
    __nv_bfloat16 h0 = __float2bfloat16(a.x), h1 = __float2bfloat16(a.y);
    __nv_bfloat16 h2 = __float2bfloat16(a.z), h3 = __float2bfloat16(a.w);
    __nv_bfloat162 hh0(h0, h1), hh1(h2, h3);
    __nv_bfloat162 ll0(__float2bfloat16(a.x - __bfloat162float(h0)),
                       __float2bfloat16(a.y - __bfloat162float(h1)));
    __nv_bfloat162 ll1(__float2bfloat16(a.z - __bfloat162float(h2)),
                       __float2bfloat16(a.w - __bfloat162float(h3)));
    ((__nv_bfloat162*)hp)[0] = hh0; ((__nv_bfloat162*)hp)[1] = hh1;
    ((__nv_bfloat162*)lp)[0] = ll0; ((__nv_bfloat162*)lp)[1] = ll1;
}
#define CP_ASYNC16(dst, src) asm volatile("cp.async.cg.shared.global [%0], [%1], 16;" :: "r"(dst), "l"(src))
#define CP_COMMIT()          asm volatile("cp.async.commit_group;")
#define CP_WAIT1()           asm volatile("cp.async.wait_group 1;")
#define CP_WAIT0()           asm volatile("cp.async.wait_group 0;")

#define PREP_GRID (2 * RELS + (RELS * C + 1 + 7) / 8)   // 55

// ---------------- device bodies ----------------
__device__ void prepall_body(int bid, int wbuf,
                             const float* __restrict__ w, const float* __restrict__ q,
                             const float* __restrict__ kk, const float* __restrict__ le,
                             const float* __restrict__ ee, float* tile) {
    __nv_bfloat16* wh = g_wts_hi + (size_t)wbuf * C * KS;
    __nv_bfloat16* wl = g_wts_lo + (size_t)wbuf * C * KS;
    if (bid < 2 * RELS) {
        int r = bid >> 1;
        int kt = (bid & 1) * 64;
        const float* Wr = w + (size_t)r * C * C;
        int tid = threadIdx.x;
#pragma unroll
        for (int it = 0; it < 8; ++it) {
            int idx = tid + it * 256;
            int kkr = idx >> 5;
            int nn4 = (idx & 31) * 4;
            float4 v = *(const float4*)(Wr + (size_t)(kt + kkr) * C + nn4);
            tile[kkr * 129 + nn4] = v.x; tile[kkr * 129 + nn4 + 1] = v.y;
            tile[kkr * 129 + nn4 + 2] = v.z; tile[kkr * 129 + nn4 + 3] = v.w;
        }
        __syncthreads();
        int lane = tid & 31, wid = tid >> 5;
        for (int nn = wid; nn < C; nn += 8) {
            float v0 = tile[(2 * lane) * 129 + nn];
            float v1 = tile[(2 * lane + 1) * 129 + nn];
            __nv_bfloat16 h0 = __float2bfloat16(v0), h1 = __float2bfloat16(v1);
            __nv_bfloat162 hh(h0, h1);
            __nv_bfloat162 ll(__float2bfloat16(v0 - __bfloat162float(h0)),
                              __float2bfloat16(v1 - __bfloat162float(h1)));
            size_t off = (size_t)nn * KS + r * C + kt + 2 * lane;
            *(__nv_bfloat162*)(wh + off) = hh;
            *(__nv_bfloat162*)(wl + off) = ll;
        }
        return;
    }
    int gw = (bid - 2 * RELS) * 8 + (threadIdx.x >> 5);
    int lane = threadIdx.x & 31;
    if (gw < RELS * C) {
        const float4* row = (const float4*)(w + (size_t)gw * C);
        float4 wv = row[lane];
        float4 qv = ((const float4*)q)[lane];
        float4 kv = ((const float4*)kk)[lane];
        float aq = wv.x * qv.x + wv.y * qv.y + wv.z * qv.z + wv.w * qv.w;
        float ak = wv.x * kv.x + wv.y * kv.y + wv.z * kv.z + wv.w * kv.w;
#pragma unroll
        for (int off = 16; off; off >>= 1) {
            aq += __shfl_xor_sync(0xffffffffu, aq, off);
            ak += __shfl_xor_sync(0xffffffffu, ak, off);
        }
        if (lane == 0) { g_wq[gw] = aq; g_wk[gw] = ak; }
    } else if (gw == RELS * C) {
        float p = 0.f;
        for (int o = lane; o < C; o += 32) p += le[o] * ee[o];
#pragma unroll
        for (int off = 16; off; off >>= 1) p += __shfl_xor_sync(0xffffffffu, p, off);
        if (lane == 0) g_cattr = p;
    }
}

__device__ void sqk_body(int gwarp, const float* __restrict__ x, int n) {
    int lane = threadIdx.x & 31;
    if (gwarp >= n) return;
    float4 xv = ((const float4*)x)[(size_t)gwarp * 32 + lane];
    float aq[RELS], ak[RELS];
#pragma unroll
    for (int r = 0; r < RELS; ++r) {
        float4 wqv = ((const float4*)g_wq)[r * 32 + lane];
        float4 wkv = ((const float4*)g_wk)[r * 32 + lane];
        aq[r] = xv.x * wqv.x + xv.y * wqv.y + xv.z * wqv.z + xv.w * wqv.w;
        ak[r] = xv.x * wkv.x + xv.y * wkv.y + xv.z * wkv.z + xv.w * wkv.w;
    }
#pragma unroll
    for (int off = 16; off; off >>= 1) {
#pragma unroll
        for (int r = 0; r < RELS; ++r) {
            aq[r] += __shfl_xor_sync(0xffffffffu, aq[r], off);
            ak[r] += __shfl_xor_sync(0xffffffffu, ak[r], off);
        }
    }
    if (lane == 0) {
#pragma unroll
        for (int r = 0; r < RELS; ++r) {
            g_sq[r * n + gwarp] = aq[r];
            g_sk[r * n + gwarp] = ak[r];
        }
    }
}

#define ACCUM(rr, co, v)                                                     \
    do {                                                                     \
        if ((rr) == 0) {                                                     \
            a0.x = fmaf(co, (v).x, a0.x); a0.y = fmaf(co, (v).y, a0.y);      \
            a0.z = fmaf(co, (v).z, a0.z); a0.w = fmaf(co, (v).w, a0.w);      \
        } else if ((rr) == 1) {                                              \
            a1.x = fmaf(co, (v).x, a1.x); a1.y = fmaf(co, (v).y, a1.y);      \
            a1.z = fmaf(co, (v).z, a1.z); a1.w = fmaf(co, (v).w, a1.w);      \
        } else {                                                             \
            a2.x = fmaf(co, (v).x, a2.x); a2.y = fmaf(co, (v).y, a2.y);      \
            a2.z = fmaf(co, (v).z, a2.z); a2.w = fmaf(co, (v).w, a2.w);      \
        }                                                                    \
    } while (0)

__device__ void agg_body(int gwarp, const float* __restrict__ xin, int n) {
    int lane = threadIdx.x & 31;
    if (gwarp >= n) return;
    int beg = g_indptr[gwarp], end = g_indptr[gwarp + 1];

    float m = -CUDART_INF_F;
    for (int j = beg + lane; j < end; j += 32) m = fmaxf(m, g_alphac[j]);
#pragma unroll
    for (int off = 16; off; off >>= 1) m = fmaxf(m, __shfl_xor_sync(0xffffffffu, m, off));

    float s = 0.f;
    for (int j = beg + lane; j < end; j += 32) s += __expf(g_alphac[j] - m);
#pragma unroll
    for (int off = 16; off; off >>= 1) s += __shfl_xor_sync(0xffffffffu, s, off);
    float inv = 1.f / (s + 1e-16f);

    float4 a0 = make_float4(0.f, 0.f, 0.f, 0.f);
    float4 a1 = a0, a2 = a0;
    int j = beg;
    for (; j + 3 < end; j += 4) {
        float al0 = g_alphac[j],     al1 = g_alphac[j + 1];
        float al2 = g_alphac[j + 2], al3 = g_alphac[j + 3];
        unsigned p0 = g_pack[j],     p1 = g_pack[j + 1];
        unsigned p2 = g_pack[j + 2], p3 = g_pack[j + 3];
        float4 v0 = ((const float4*)(xin + (size_t)(p0 & 0x0FFFFFFFu) * C))[lane];
        float4 v1 = ((const float4*)(xin + (size_t)(p1 & 0x0FFFFFFFu) * C))[lane];
        float4 v2 = ((const float4*)(xin + (size_t)(p2 & 0x0FFFFFFFu) * C))[lane];
        float4 v3 = ((const float4*)(xin + (size_t)(p3 & 0x0FFFFFFFu) * C))[lane];
        float c0 = __expf(al0 - m) * inv, c1 = __expf(al1 - m) * inv;
        float c2 = __expf(al2 - m) * inv, c3 = __expf(al3 - m) * inv;
        ACCUM(p0 >> 28, c0, v0);
        ACCUM(p1 >> 28, c1, v1);
        ACCUM(p2 >> 28, c2, v2);
        ACCUM(p3 >> 28, c3, v3);
    }
    for (; j < end; ++j) {
        float al0 = g_alphac[j];
        unsigned p0 = g_pack[j];
        float4 v0 = ((const float4*)(xin + (size_t)(p0 & 0x0FFFFFFFu) * C))[lane];
        float c0 = __expf(al0 - m) * inv;
        ACCUM(p0 >> 28, c0, v0);
    }
    size_t ob = (size_t)gwarp * KS + (size_t)lane * 4;
    store_split(g_agg_hi + ob,         g_agg_lo + ob,         a0);
    store_split(g_agg_hi + ob + C,     g_agg_lo + ob + C,     a1);
    store_split(g_agg_hi + ob + 2 * C, g_agg_lo + ob + 2 * C, a2);
}

// ---------------- fused kernels ----------------
__global__ void k_cnt_prep(const int* __restrict__ dst, int e_cnt,
                           const float* __restrict__ w, const float* __restrict__ q,
                           const float* __restrict__ kk, const float* __restrict__ le,
                           const float* __restrict__ ee, int wbuf) {
    __shared__ float tile[64 * 129];
    if (blockIdx.x < PREP_GRID) {
        prepall_body(blockIdx.x, wbuf, w, q, kk, le, ee, tile);
        return;
    }
    int e = (blockIdx.x - PREP_GRID) * blockDim.x + threadIdx.x;
    if (e < e_cnt) atomicAdd(&g_deg[dst[e]], 1);
}

__global__ void k_scanA(int n) {
    __shared__ int sh[2][1024];
    int tid = threadIdx.x;
    int i = blockIdx.x * 1024 + tid;
    int v = (i < n) ? g_deg[i] : 0;
    sh[0][tid] = v;
    __syncthreads();
    int pb = 0;
#pragma unroll
    for (int off = 1; off < 1024; off <<= 1) {
        int nb = pb ^ 1;
        int val = sh[pb][tid];
        if (tid >= off) val += sh[pb][tid - off];
        sh[nb][tid] = val;
        pb = nb;
        __syncthreads();
    }
    int incl = sh[pb][tid];
    if (i < n) g_incl[i] = incl;
    if (tid == 1023) g_bsum[blockIdx.x] = incl;
}
__global__ void k_scanC(int n, int nblk) {
    __shared__ int sb[64];
    int tid = threadIdx.x;
    int bid = blockIdx.x;
    if (tid < 64) sb[tid] = (tid < nblk) ? g_bsum[tid] : 0;
    __syncthreads();
#pragma unroll
    for (int off = 1; off < 64; off <<= 1) {
        int add = (tid < 64 && tid >= off) ? sb[tid - off] : 0;
        __syncthreads();
        if (tid < 64) sb[tid] += add;
        __syncthreads();
    }
    int base = (bid == 0) ? 0 : sb[bid - 1];
    int i = bid * 1024 + tid;
    if (i < n) {
        int total = g_incl[i] + base;
        g_indptr[i + 1] = total;
        g_cursor[i] = total - g_deg[i];
        g_deg[i] = 0;
        if (i == 0) g_indptr[0] = 0;
    }
}

__global__ void k_fill_sqk(const int* __restrict__ src, const int* __restrict__ dst,
                           const int* __restrict__ etype, const float* __restrict__ attr,
                           int e_cnt, const float* __restrict__ x, int n, int sqk_grid) {
    if ((int)blockIdx.x < sqk_grid) {
        int gwarp = blockIdx.x * 8 + (threadIdx.x >> 5);
        sqk_body(gwarp, x, n);
        return;
    }
    int e = (blockIdx.x - sqk_grid) * blockDim.x + threadIdx.x;
    if (e >= e_cnt) return;
    int d = dst[e];
    int pos = atomicAdd(&g_cursor[d], 1);
    g_pack[pos] = (unsigned)src[e] | ((unsigned)etype[e] << 28);
    g_attrc[pos] = attr[e];
    g_dstc[pos] = d;
}

__global__ void k_alphac(int n, int e_cnt) {
    int pos = blockIdx.x * blockDim.x + threadIdx.x;
    if (pos >= e_cnt) return;
    unsigned p = g_pack[pos];
    unsigned sv = p & 0x0FFFFFFFu, r = p >> 28;
    int d = g_dstc[pos];
    float a = g_sq[r * n + d] + g_sk[r * n + sv] + g_cattr * g_attrc[pos];
    g_alphac[pos] = (a > 0.f) ? a : 0.2f * a;
}

__global__ void k_agg_prep(const float* __restrict__ xin, int n, int agg_grid,
                           const float* __restrict__ w, const float* __restrict__ q,
                           const float* __restrict__ kk, const float* __restrict__ le,
                           const float* __restrict__ ee, int wbuf) {
    __shared__ float tile[64 * 129];
    if ((int)blockIdx.x >= agg_grid) {
        prepall_body(blockIdx.x - agg_grid, wbuf, w, q, kk, le, ee, tile);
        return;
    }
    int gwarp = blockIdx.x * 8 + (threadIdx.x >> 5);
    agg_body(gwarp, xin, n);
}

__global__ void k_agg(const float* __restrict__ xin, int n) {
    int gwarp = blockIdx.x * 8 + (threadIdx.x >> 5);
    agg_body(gwarp, xin, n);
}

// ---------------- stacked HMMA bf16 3-term GEMM, cp.async double-buffered ----------------
// do_sqk: fuse next-layer sq/sk computation from output rows (uses current g_wq/g_wk).
#define KC 32
#define NCH (KS / KC)
#define AST 40
#define STAGE_B 40960
#define ARR_B 10240
#define GEMM_SMEM (2 * STAGE_B)

__global__ __launch_bounds__(256, 2) void k_gemm_st(const float* __restrict__ bias,
                                                    float* __restrict__ out,
                                                    int relu, int n, int wbuf, int do_sqk) {
    extern __shared__ __nv_bfloat16 smb[];
    uint32_t smemu = smem_u32(smb);
    const __nv_bfloat16* wth = g_wts_hi + (size_t)wbuf * C * KS;
    const __nv_bfloat16* wtl = g_wts_lo + (size_t)wbuf * C * KS;

    int m0 = blockIdx.x * 128;
    int tid = threadIdx.x;
    int lane = tid & 31;
    int wid = tid >> 5;
    int wm = wid & 1;
    int wn = wid >> 1;

    int lrow = (lane & 7) + ((lane >> 3) & 1) * 8;
    int lkoff = (lane >> 4) * 8;
    uint32_t baseA = (uint32_t)((wm * 64 + lrow) * AST + lkoff) * 2;
    uint32_t baseB = (uint32_t)((wn * 32 + lrow) * AST + lkoff) * 2;

    float acc[4][4][4];
#pragma unroll
    for (int a = 0; a < 4; ++a)
#pragma unroll
        for (int b = 0; b < 4; ++b)
#pragma unroll
            for (int cc = 0; cc < 4; ++cc) acc[a][b][cc] = 0.f;

    int u = tid & 3;
    int row2 = tid >> 2;

    auto load_chunk = [&](int c, int st) {
        int kc = c * KC;
        uint32_t sb = smemu + (uint32_t)st * STAGE_B;
#pragma unroll
        for (int it = 0; it < 2; ++it) {
            int row = row2 + it * 64;
            uint32_t doff = (uint32_t)(row * 80 + u * 16);
            if (m0 + row < n) {
                size_t g = (size_t)(m0 + row) * KS + kc + u * 8;
                CP_ASYNC16(sb + doff, g_agg_hi + g);
                CP_ASYNC16(sb + ARR_B + doff, g_agg_lo + g);
            } else {
                *(uint4*)((char*)smb + st * STAGE_B + doff) = make_uint4(0u, 0u, 0u, 0u);
                *(uint4*)((char*)smb + st * STAGE_B + ARR_B + doff) = make_uint4(0u, 0u, 0u, 0u);
            }
            size_t gb = (size_t)row * KS + kc + u * 8;
            CP_ASYNC16(sb + 2 * ARR_B + doff, wth + gb);
            CP_ASYNC16(sb + 3 * ARR_B + doff, wtl + gb);
        }
    };

    load_chunk(0, 0);
    CP_COMMIT();

#pragma unroll 1
    for (int c = 0; c < NCH; ++c) {
        int st = c & 1;
        if (c + 1 < NCH) {
            load_chunk(c + 1, st ^ 1);
            CP_COMMIT();
            CP_WAIT1();
        } else {
            CP_WAIT0();
        }
        __syncthreads();

        uint32_t sA = smemu + (uint32_t)st * STAGE_B;
        uint32_t sAl = sA + ARR_B, sBh = sA + 2 * ARR_B, sBl = sA + 3 * ARR_B;
#pragma unroll
        for (int ks = 0; ks < 2; ++ks) {
            uint32_t koff = (uint32_t)(ks * 16) * 2;
            uint32_t ah[4][4], al[4][4], bh[4][2], bl[4][2];
#pragma unroll
            for (int mt = 0; mt < 4; ++mt) {
                ldsm_x4(ah[mt], sA + baseA + koff + (uint32_t)(mt * 16 * AST * 2));
                ldsm_x4(al[mt], sAl + baseA + koff + (uint32_t)(mt * 16 * AST * 2));
            }
#pragma unroll
            for (int p = 0; p < 2; ++p) {
                uint32_t t4[4];
                ldsm_x4(t4, sBh + baseB + koff + (uint32_t)(p * 16 * AST * 2));
                bh[2 * p][0] = t4[0]; bh[2 * p + 1][0] = t4[1];
                bh[2 * p][1] = t4[2]; bh[2 * p + 1][1] = t4[3];
                ldsm_x4(t4, sBl + baseB + koff + (uint32_t)(p * 16 * AST * 2));
                bl[2 * p][0] = t4[0]; bl[2 * p + 1][0] = t4[1];
                bl[2 * p][1] = t4[2]; bl[2 * p + 1][1] = t4[3];
            }
#pragma unroll
            for (int mt = 0; mt < 4; ++mt)
#pragma unroll
                for (int nt = 0; nt < 4; ++nt) mma_bf16(acc[mt][nt], ah[mt], bh[nt]);
#pragma unroll
            for (int mt = 0; mt < 4; ++mt)
#pragma unroll
                for (int nt = 0; nt < 4; ++nt) mma_bf16(acc[mt][nt], ah[mt], bl[nt]);
#pragma unroll
            for (int mt = 0; mt < 4; ++mt)
#pragma unroll
                for (int nt = 0; nt < 4; ++nt) mma_bf16(acc[mt][nt], al[mt], bh[nt]);
        }
        __syncthreads();
    }

    // ---- epilogue: + bias, optional relu, optional fused next-layer sqk ----
    float bx[4][2];
#pragma unroll
    for (int nt = 0; nt < 4; ++nt) {
        int col = wn * 32 + nt * 8 + 2 * (lane & 3);
        bx[nt][0] = bias[col];
        bx[nt][1] = bias[col + 1];
    }
    // reused smem for sqk reduction: [128 rows][3 rels][2 qk][4 warps]
    float* sred = (float*)smb;

#pragma unroll
    for (int mt = 0; mt < 4; ++mt) {
        int rl0 = wm * 64 + mt * 16 + (lane >> 2);
        int rl1 = rl0 + 8;
        int row0 = m0 + rl0, row1 = row0 + 8;
        float pq0[3] = {0.f, 0.f, 0.f}, pk0[3] = {0.f, 0.f, 0.f};
        float pq1[3] = {0.f, 0.f, 0.f}, pk1[3] = {0.f, 0.f, 0.f};
#pragma unroll
        for (int nt = 0; nt < 4; ++nt) {
            int col = wn * 32 + nt * 8 + 2 * (lane & 3);
            float2 o0 = make_float2(acc[mt][nt][0] + bx[nt][0], acc[mt][nt][1] + bx[nt][1]);
            float2 o1 = make_float2(acc[mt][nt][2] + bx[nt][0], acc[mt][nt][3] + bx[nt][1]);
            if (relu) {
                o0.x = fmaxf(o0.x, 0.f); o0.y = fmaxf(o0.y, 0.f);
                o1.x = fmaxf(o1.x, 0.f); o1.y = fmaxf(o1.y, 0.f);
            }
            if (row0 < n) *(float2*)(out + (size_t)row0 * C + col) = o0;
            if (row1 < n) *(float2*)(out + (size_t)row1 * C + col) = o1;
            if (do_sqk) {
#pragma unroll
                for (int r = 0; r < RELS; ++r) {
                    float wq0 = g_wq[r * C + col], wq1 = g_wq[r * C + col + 1];
                    float wk0 = g_wk[r * C + col], wk1 = g_wk[r * C + col + 1];
                    pq0[r] += o0.x * wq0 + o0.y * wq1;
                    pk0[r] += o0.x * wk0 + o0.y * wk1;
                    pq1[r] += o1.x * wq0 + o1.y * wq1;
                    pk1[r] += o1.x * wk0 + o1.y * wk1;
                }
            }
        }
        if (do_sqk) {
            // reduce over the quad (lane&3): lanes share rows, cover distinct col pairs
#pragma unroll
            for (int r = 0; r < RELS; ++r) {
                pq0[r] += __shfl_xor_sync(0xffffffffu, pq0[r], 1);
                pq0[r] += __shfl_xor_sync(0xffffffffu, pq0[r], 2);
                pk0[r] += __shfl_xor_sync(0xffffffffu, pk0[r], 1);
                pk0[r] += __shfl_xor_sync(0xffffffffu, pk0[r], 2);
                pq1[r] += __shfl_xor_sync(0xffffffffu, pq1[r], 1);
                pq1[r] += __shfl_xor_sync(0xffffffffu, pq1[r], 2);
                pk1[r] += __shfl_xor_sync(0xffffffffu, pk1[r], 1);
                pk1[r] += __shfl_xor_sync(0xffffffffu, pk1[r], 2);
            }
            if ((lane & 3) == 0) {
#pragma unroll
                for (int r = 0; r < RELS; ++r) {
                    sred[((rl0 * 3 + r) * 2 + 0) * 4 + wn] = pq0[r];
                    sred[((rl0 * 3 + r) * 2 + 1) * 4 + wn] = pk0[r];
                    sred[((rl1 * 3 + r) * 2 + 0) * 4 + wn] = pq1[r];
                    sred[((rl1 * 3 + r) * 2 + 1) * 4 + wn] = pk1[r];
                }
            }
        }
    }
    if (do_sqk) {
        __syncthreads();
        if (tid < 128) {
            int grow = m0 + tid;
            if (grow < n) {
#pragma unroll
                for (int r = 0; r < RELS; ++r) {
                    float* pq = &sred[((tid * 3 + r) * 2 + 0) * 4];
                    float* pk = &sred[((tid * 3 + r) * 2 + 1) * 4];
                    g_sq[r * n + grow] = pq[0] + pq[1] + pq[2] + pq[3];
                    g_sk[r * n + grow] = pk[0] + pk[1] + pk[2] + pk[3];
                }
            }
        }
    }
}

// ---------------- driver ----------------
extern "C" void kernel_launch(void* const* d_in, const int* in_sizes, int n_in,
                              void* d_out, int out_size) {
    const float* x    = (const float*)d_in[0];
    const int*   ei   = (const int*)d_in[1];
    const int*   et   = (const int*)d_in[2];
    const float* attr = (const float*)d_in[3];
    const float *w1 = (const float*)d_in[4],  *q1 = (const float*)d_in[5],
                *k1 = (const float*)d_in[6],  *le1 = (const float*)d_in[7],
                *e1 = (const float*)d_in[8],  *b1 = (const float*)d_in[9];
    const float *w2 = (const float*)d_in[10], *q2 = (const float*)d_in[11],
                *k2 = (const float*)d_in[12], *le2 = (const float*)d_in[13],
                *e2 = (const float*)d_in[14], *b2 = (const float*)d_in[15];

    int n = in_sizes[0] / C;
    int e_cnt = in_sizes[2];
    const int* src = ei;
    const int* dst = ei + e_cnt;

    float* h = nullptr;
    cudaGetSymbolAddress((void**)&h, g_h);

    static bool attr_set = false;
    if (!attr_set) {
        cudaFuncSetAttribute(k_gemm_st, cudaFuncAttributeMaxDynamicSharedMemorySize, GEMM_SMEM);
        attr_set = true;
    }

    int nblk = (n + 1023) / 1024;
    int gemm_grid = (n + 127) / 128;
    int eb = (e_cnt + 255) / 256;
    int ng = (n + 7) / 8;

    // 1: prepall(L1, buf0) + count
    k_cnt_prep<<<PREP_GRID + eb, 256>>>(dst, e_cnt, w1, q1, k1, le1, e1, 0);
    // 2,3: scan
    k_scanA<<<nblk, 1024>>>(n);
    k_scanC<<<nblk, 1024>>>(n, nblk);
    // 4: sqk(L1) + fill
    k_fill_sqk<<<ng + eb, 256>>>(src, dst, et, attr, e_cnt, x, n, ng);
    // 5: alpha(L1)
    k_alphac<<<eb, 256>>>(n, e_cnt);
    // 6: agg(L1) + prepall(L2, buf1) — installs layer-2 wq/wk for gemm1's fused sqk
    k_agg_prep<<<ng + PREP_GRID, 256>>>(x, n, ng, w2, q2, k2, le2, e2, 1);
    // 7: gemm(L1, buf0) with fused sqk(L2)
    k_gemm_st<<<gemm_grid, 256, GEMM_SMEM>>>(b1, h, 1, n, 0, 1);
    // 8-10: layer 2
    k_alphac<<<eb, 256>>>(n, e_cnt);
    k_agg<<<ng, 256>>>(h, n);
    k_gemm_st<<<gemm_grid, 256, GEMM_SMEM>>>(b2, (float*)d_out, 0, n, 1, 0);
}